// round 14
// baseline (speedup 1.0000x reference)
#include <cuda_runtime.h>
#include <cuda_bf16.h>
#include <math.h>
#include <stdint.h>

#define NB 1024
#define FC_KSPLIT 14
#define FC_KC 224      // 3136 / 14

// -------- scratch (static __device__ globals; zero-initialized, no allocation) --------
#define P1C_MARGIN_E 2048              // 64 rows * 32 elements
__device__ __align__(16) __nv_bfloat16 g_p1ch[P1C_MARGIN_E + 1024 * 256 * 32 + P1C_MARGIN_E];
__device__ __align__(16) __nv_bfloat16 g_p1cl[P1C_MARGIN_E + 1024 * 256 * 32 + P1C_MARGIN_E];
__device__ __align__(16) __nv_bfloat16 g_p2h[NB * 3136];      // pool2 out bf16 hi (NCHW-flat)
__device__ __align__(16) __nv_bfloat16 g_p2l[NB * 3136];      // pool2 out bf16 lo
__device__ __align__(16) __nv_bfloat16 g_fwh[256 * 3136];     // fc weights bf16 hi
__device__ __align__(16) __nv_bfloat16 g_fwl[256 * 3136];     // fc weights bf16 lo
__device__ __align__(16) float g_fpart[FC_KSPLIT * NB * 256]; // FC split-K partials
__device__ __align__(16) __nv_bfloat16 g_w2bh[9 * 64 * 32];   // conv2 weights bf16 hi [pos][oc][ic]
__device__ __align__(16) __nv_bfloat16 g_w2bl[9 * 64 * 32];   // conv2 weights bf16 lo
__device__ __align__(16) uint2 g_w2bhf[9 * 2 * 32 * 8];       // fragment-order hi [pos][s][lane][j]
__device__ __align__(16) uint2 g_w2blf[9 * 2 * 32 * 8];       // fragment-order lo
__device__ float g_b2r[64];                                   // conv2 bias, BN-folded

// ==================== warp-level bf16 HMMA + ldmatrix (baseline PTX) ====================
__device__ __forceinline__ void mma16816(float* c, uint32_t a0, uint32_t a1, uint32_t a2,
                                         uint32_t a3, uint32_t b0, uint32_t b1) {
    asm volatile(
        "mma.sync.aligned.m16n8k16.row.col.f32.bf16.bf16.f32 "
        "{%0,%1,%2,%3}, {%4,%5,%6,%7}, {%8,%9}, {%0,%1,%2,%3};"
        : "+f"(c[0]), "+f"(c[1]), "+f"(c[2]), "+f"(c[3])
        : "r"(a0), "r"(a1), "r"(a2), "r"(a3), "r"(b0), "r"(b1));
}
__device__ __forceinline__ void ldsm4(uint32_t* r, const __nv_bfloat16* p) {
    uint32_t a = (uint32_t)__cvta_generic_to_shared(p);
    asm volatile("ldmatrix.sync.aligned.m8n8.x4.shared.b16 {%0,%1,%2,%3}, [%4];"
                 : "=r"(r[0]), "=r"(r[1]), "=r"(r[2]), "=r"(r[3]) : "r"(a));
}
__device__ __forceinline__ uint2 hi2(float4 v) {
    __nv_bfloat16 h0 = __float2bfloat16(v.x), h1 = __float2bfloat16(v.y);
    __nv_bfloat16 h2 = __float2bfloat16(v.z), h3 = __float2bfloat16(v.w);
    return make_uint2((uint32_t)__bfloat16_as_ushort(h0) | ((uint32_t)__bfloat16_as_ushort(h1) << 16),
                      (uint32_t)__bfloat16_as_ushort(h2) | ((uint32_t)__bfloat16_as_ushort(h3) << 16));
}
__device__ __forceinline__ uint2 lo2(float4 v) {
    __nv_bfloat16 h0 = __float2bfloat16(v.x), h1 = __float2bfloat16(v.y);
    __nv_bfloat16 h2 = __float2bfloat16(v.z), h3 = __float2bfloat16(v.w);
    __nv_bfloat16 l0 = __float2bfloat16(v.x - __bfloat162float(h0));
    __nv_bfloat16 l1 = __float2bfloat16(v.y - __bfloat162float(h1));
    __nv_bfloat16 l2 = __float2bfloat16(v.z - __bfloat162float(h2));
    __nv_bfloat16 l3 = __float2bfloat16(v.w - __bfloat162float(h3));
    return make_uint2((uint32_t)__bfloat16_as_ushort(l0) | ((uint32_t)__bfloat16_as_ushort(l1) << 16),
                      (uint32_t)__bfloat16_as_ushort(l2) | ((uint32_t)__bfloat16_as_ushort(l3) << 16));
}

// ==================== conv2 weight repack + BN fold -> bf16 hi/lo [pos][oc][ic] ====================
__global__ void repack_k(const float* __restrict__ w2, const float* __restrict__ b2,
                         const float* __restrict__ gm, const float* __restrict__ bt,
                         const float* __restrict__ mu, const float* __restrict__ vr) {
    int i = blockIdx.x * blockDim.x + threadIdx.x;
    if (i < 64 * 32 * 9) {
        int oc = i / 288;
        int r  = i % 288;
        int ic = r / 9, k = r % 9;
        float sc = gm[oc] / sqrtf(vr[oc] + 1e-5f);
        float w = w2[i] * sc;
        __nv_bfloat16 h = __float2bfloat16(w);
        __nv_bfloat16 l = __float2bfloat16(w - __bfloat162float(h));
        g_w2bh[(k * 64 + oc) * 32 + ic] = h;
        g_w2bl[(k * 64 + oc) * 32 + ic] = l;
    }
    if (i < 64) {
        float sc = gm[i] / sqrtf(vr[i] + 1e-5f);
        g_b2r[i] = b2[i] * sc + bt[i] - mu[i] * sc;
    }
}

// ==================== conv2 weights -> fragment order [pos][s][lane][j] (uint2) ====================
__global__ void frepack_k() {
    int i = blockIdx.x * blockDim.x + threadIdx.x;   // 4608 = 9*2*32*8
    if (i < 4608) {
        int j = i & 7, lane = (i >> 3) & 31, ps = i >> 8;  // ps = pos*2+s
        int pos = ps >> 1, s = ps & 1;
        int gr = lane >> 2, ct = lane & 3;
        int row = pos * 64 + j * 8 + gr;
        int c0 = s * 16 + ct * 2;
        const __nv_bfloat16* h = g_w2bh + row * 32 + c0;
        const __nv_bfloat16* l = g_w2bl + row * 32 + c0;
        g_w2bhf[i] = make_uint2(*(const uint32_t*)h, *(const uint32_t*)(h + 8));
        g_w2blf[i] = make_uint2(*(const uint32_t*)l, *(const uint32_t*)(l + 8));
    }
}

// ==================== fc weight bf16 hi/lo pre-split ====================
__global__ void wrepack_k(const float* __restrict__ fw) {
    int i = blockIdx.x * blockDim.x + threadIdx.x;   // 200704 = 256*3136/4
    if (i < 200704) {
        float4 v = ((const float4*)fw)[i];
        *(uint2*)(g_fwh + i * 4) = hi2(v);
        *(uint2*)(g_fwl + i * 4) = lo2(v);
    }
}

// ==================== conv1 + bn + relu + maxpool -> channel-last padded bf16 hi/lo ====================
__global__ void conv1_k(const float* __restrict__ x,  const float* __restrict__ w1,
                        const float* __restrict__ b1, const float* __restrict__ gm,
                        const float* __restrict__ bt, const float* __restrict__ mu,
                        const float* __restrict__ vr) {
    __shared__ float si[30][32];
    __shared__ float sw[288];
    __shared__ float sa[32], sb[32];
    int b = blockIdx.x, tid = threadIdx.x;
    for (int i = tid; i < 30 * 32; i += 256) ((float*)si)[i] = 0.f;
    __syncthreads();
    for (int i = tid; i < 784; i += 256) {
        int y = i / 28, xx = i % 28;
        si[y + 1][xx + 1] = x[b * 784 + i];
    }
    for (int i = tid; i < 288; i += 256) sw[i] = w1[i];
    if (tid < 32) {
        float sc = gm[tid] / sqrtf(vr[tid] + 1e-5f);
        sa[tid] = sc;
        sb[tid] = b1[tid] * sc + bt[tid] - mu[tid] * sc;
    }
    __syncthreads();

    for (int idx = tid; idx < 32 * 196; idx += 256) {
        int c = idx & 31, pp = idx >> 5;
        int py = pp / 14, px = pp % 14;
        int iy = 2 * py, ix = 2 * px;
        float wk[9];
#pragma unroll
        for (int k = 0; k < 9; k++) wk[k] = sw[c * 9 + k];
        float p[4][4];
#pragma unroll
        for (int r = 0; r < 4; r++)
#pragma unroll
            for (int cc = 0; cc < 4; cc++) p[r][cc] = si[iy + r][ix + cc];
        float v00 = 0.f, v01 = 0.f, v10 = 0.f, v11 = 0.f;
#pragma unroll
        for (int ky = 0; ky < 3; ky++)
#pragma unroll
            for (int kx = 0; kx < 3; kx++) {
                float w = wk[ky * 3 + kx];
                v00 += w * p[ky][kx];     v01 += w * p[ky][kx + 1];
                v10 += w * p[ky + 1][kx]; v11 += w * p[ky + 1][kx + 1];
            }
        float sc = sa[c], sh = sb[c];
        float m = fmaxf(fmaxf(v00 * sc + sh, v01 * sc + sh),
                        fmaxf(v10 * sc + sh, v11 * sc + sh));
        float v = fmaxf(m, 0.f);
        __nv_bfloat16 h = __float2bfloat16(v);
        __nv_bfloat16 l = __float2bfloat16(v - __bfloat162float(h));
        int row = b * 256 + (py + 1) * 16 + (px + 1);
        g_p1ch[P1C_MARGIN_E + row * 32 + c] = h;
        g_p1cl[P1C_MARGIN_E + row * 32 + c] = l;
    }
}

// ==================== conv2: bf16 hi/lo 3-set implicit GEMM; A via ldmatrix, B via frag-LDG ====================
#define A_STRIDE 40
#define OFF_AHI  512
#define OFF_ALO  (OFF_AHI + 290 * A_STRIDE * 2)     // 23712
#define CV2_SMEM 70656                              // covers staging (46912) and D epilogue (512+69632)

__global__ void __launch_bounds__(256, 2) conv2mma_k() {
    extern __shared__ char smem[];
    int tid = threadIdx.x, wid = tid >> 5, lane = tid & 31;
    int b = blockIdx.x;
    float* sbias = (float*)smem;
    if (tid < 64) sbias[tid] = g_b2r[tid];

    __nv_bfloat16* sAh = (__nv_bfloat16*)(smem + OFF_AHI);
    __nv_bfloat16* sAl = (__nv_bfloat16*)(smem + OFF_ALO);

    // stage A: pure uint4 copies (conv1 pre-split bf16 hi/lo)
    long arow0 = (long)b * 256 - 17;
    const __nv_bfloat16* ah_base = g_p1ch + P1C_MARGIN_E + arow0 * 32;
    const __nv_bfloat16* al_base = g_p1cl + P1C_MARGIN_E + arow0 * 32;
    for (int u = tid; u < 290 * 4; u += 256) {
        int rr = u >> 2, c8 = u & 3;
        *(uint4*)(sAh + rr * A_STRIDE + c8 * 8) = *(const uint4*)(ah_base + rr * 32 + c8 * 8);
        *(uint4*)(sAl + rr * A_STRIDE + c8 * 8) = *(const uint4*)(al_base + rr * 32 + c8 * 8);
    }
    __syncthreads();

    int gr = lane >> 2, ct = lane & 3;
    int r_ = lane & 7, sel = lane >> 3;
    int a_roff = ((sel & 1) << 3) + r_;
    int a_koff = (sel >> 1) << 3;

    float acc[2][8][4];
#pragma unroll
    for (int mt = 0; mt < 2; mt++)
#pragma unroll
        for (int j = 0; j < 8; j++)
#pragma unroll
            for (int q = 0; q < 4; q++) acc[mt][j][q] = 0.f;

    int r0 = wid * 32;
#pragma unroll
    for (int pos = 0; pos < 9; pos++) {
        int ky = pos / 3, kx = pos % 3;
        int arow = r0 + (ky - 1) * 16 + (kx - 1) + 17;
#pragma unroll
        for (int s = 0; s < 2; s++) {
            int kb = s * 16;
            // B fragments: 4+4 LDG.128, coalesced, L1-resident weight tables
            const uint4* bhp = (const uint4*)(g_w2bhf + ((pos * 2 + s) * 32 + lane) * 8);
            const uint4* blp = (const uint4*)(g_w2blf + ((pos * 2 + s) * 32 + lane) * 8);
            uint4 h0 = bhp[0], h1 = bhp[1], h2 = bhp[2], h3 = bhp[3];
            uint4 l0 = blp[0], l1 = blp[1], l2 = blp[2], l3 = blp[3];
            uint32_t bh[8][2] = {{h0.x,h0.y},{h0.z,h0.w},{h1.x,h1.y},{h1.z,h1.w},
                                 {h2.x,h2.y},{h2.z,h2.w},{h3.x,h3.y},{h3.z,h3.w}};
            uint32_t bl[8][2] = {{l0.x,l0.y},{l0.z,l0.w},{l1.x,l1.y},{l1.z,l1.w},
                                 {l2.x,l2.y},{l2.z,l2.w},{l3.x,l3.y},{l3.z,l3.w}};
            uint32_t ah[2][4], al[2][4];
#pragma unroll
            for (int mt = 0; mt < 2; mt++) {
                const __nv_bfloat16* pa = sAh + (arow + mt * 16 + a_roff) * A_STRIDE + kb + a_koff;
                ldsm4(ah[mt], pa);
                ldsm4(al[mt], pa + (OFF_ALO - OFF_AHI) / 2);
            }

            // pass-major MMA: each acc touched once per 16-MMA sweep (no RAW chains)
#pragma unroll
            for (int mt = 0; mt < 2; mt++)
#pragma unroll
                for (int j = 0; j < 8; j++)
                    mma16816(acc[mt][j], ah[mt][0], ah[mt][1], ah[mt][2], ah[mt][3],
                             bh[j][0], bh[j][1]);
#pragma unroll
            for (int mt = 0; mt < 2; mt++)
#pragma unroll
                for (int j = 0; j < 8; j++)
                    mma16816(acc[mt][j], ah[mt][0], ah[mt][1], ah[mt][2], ah[mt][3],
                             bl[j][0], bl[j][1]);
#pragma unroll
            for (int mt = 0; mt < 2; mt++)
#pragma unroll
                for (int j = 0; j < 8; j++)
                    mma16816(acc[mt][j], al[mt][0], al[mt][1], al[mt][2], al[mt][3],
                             bh[j][0], bh[j][1]);
        }
    }

    __syncthreads();
    float* D = (float*)(smem + OFF_AHI);
#pragma unroll
    for (int mt = 0; mt < 2; mt++)
#pragma unroll
        for (int j = 0; j < 8; j++) {
            int row = r0 + mt * 16 + gr;
            int col = j * 8 + ct * 2;
            *(float2*)(D + row * 68 + col)        = make_float2(acc[mt][j][0], acc[mt][j][1]);
            *(float2*)(D + (row + 8) * 68 + col)  = make_float2(acc[mt][j][2], acc[mt][j][3]);
        }
    __syncthreads();

    // epilogue: bias+relu+pool, write bf16 hi/lo (fc input) directly
    for (int idx = tid; idx < 64 * 49; idx += 256) {
        int oc = idx / 49, t = idx - oc * 49;
        int py = t / 7, px = t - py * 7;
        int s = (2 * py + 1) * 16 + (2 * px + 1);
        float v0 = D[s * 68 + oc];
        float v1 = D[(s + 1) * 68 + oc];
        float v2 = D[(s + 16) * 68 + oc];
        float v3 = D[(s + 17) * 68 + oc];
        float v = fmaxf(fmaxf(fmaxf(v0, v1), fmaxf(v2, v3)) + sbias[oc], 0.f);
        __nv_bfloat16 h = __float2bfloat16(v);
        __nv_bfloat16 l = __float2bfloat16(v - __bfloat162float(h));
        int o = b * 3136 + oc * 49 + t;
        g_p2h[o] = h;
        g_p2l[o] = l;
    }
}

// ==================== FC 3136 -> 256, split-K(14) bf16 hi/lo 3-pass HMMA (scalar frags) ====================
#define FCS 40
__global__ void __launch_bounds__(256) fc_mma_k() {
    __shared__ __nv_bfloat16 sAh[128 * FCS], sAl[128 * FCS];
    __shared__ __nv_bfloat16 sWh[64 * FCS],  sWl[64 * FCS];
    int tid = threadIdx.x, wid = tid >> 5, lane = tid & 31;
    int bm = blockIdx.x * 128, bn = blockIdx.y * 64, kz = blockIdx.z;
    int wm = wid & 3, wn = wid >> 2;
    int gr = lane >> 2, ct = lane & 3;

    float acc[2][4][4];
#pragma unroll
    for (int mt = 0; mt < 2; mt++)
#pragma unroll
        for (int n = 0; n < 4; n++)
#pragma unroll
            for (int q = 0; q < 4; q++) acc[mt][n][q] = 0.f;

    int k0 = kz * FC_KC;
    for (int kt = 0; kt < FC_KC / 32; kt++, k0 += 32) {
#pragma unroll
        for (int u = tid; u < 512; u += 256) {
            int row = u >> 2, c8 = u & 3;
            long g = (long)(bm + row) * 3136 + k0 + c8 * 8;
            *(uint4*)(sAh + row * FCS + c8 * 8) = *(const uint4*)(g_p2h + g);
            *(uint4*)(sAl + row * FCS + c8 * 8) = *(const uint4*)(g_p2l + g);
        }
#pragma unroll
        for (int u = tid; u < 256; u += 256) {
            int row = u >> 2, c8 = u & 3;
            long g = (long)(bn + row) * 3136 + k0 + c8 * 8;
            *(uint4*)(sWh + row * FCS + c8 * 8) = *(const uint4*)(g_fwh + g);
            *(uint4*)(sWl + row * FCS + c8 * 8) = *(const uint4*)(g_fwl + g);
        }
        __syncthreads();

#pragma unroll
        for (int s = 0; s < 2; s++) {
            int kb = s * 16;
            uint32_t ah[2][4], al[2][4], wh[4][2], wl[4][2];
#pragma unroll
            for (int mt = 0; mt < 2; mt++) {
                const __nv_bfloat16* p = sAh + (wm * 32 + mt * 16 + gr) * FCS + kb + ct * 2;
                ah[mt][0] = *(const uint32_t*)p;
                ah[mt][1] = *(const uint32_t*)(p + 8 * FCS);
                ah[mt][2] = *(const uint32_t*)(p + 8);
                ah[mt][3] = *(const uint32_t*)(p + 8 * FCS + 8);
                const __nv_bfloat16* q = sAl + (wm * 32 + mt * 16 + gr) * FCS + kb + ct * 2;
                al[mt][0] = *(const uint32_t*)q;
                al[mt][1] = *(const uint32_t*)(q + 8 * FCS);
                al[mt][2] = *(const uint32_t*)(q + 8);
                al[mt][3] = *(const uint32_t*)(q + 8 * FCS + 8);
            }
#pragma unroll
            for (int n = 0; n < 4; n++) {
                const __nv_bfloat16* p = sWh + (wn * 32 + n * 8 + gr) * FCS + kb + ct * 2;
                wh[n][0] = *(const uint32_t*)p;
                wh[n][1] = *(const uint32_t*)(p + 8);
                const __nv_bfloat16* q = sWl + (wn * 32 + n * 8 + gr) * FCS + kb + ct * 2;
                wl[n][0] = *(const uint32_t*)q;
                wl[n][1] = *(const uint32_t*)(q + 8);
            }
#pragma unroll
            for (int mt = 0; mt < 2; mt++)
#pragma unroll
                for (int n = 0; n < 4; n++)
                    mma16816(acc[mt][n], ah[mt][0], ah[mt][1], ah[mt][2], ah[mt][3], wh[n][0], wh[n][1]);
#pragma unroll
            for (int mt = 0; mt < 2; mt++)
#pragma unroll
                for (int n = 0; n < 4; n++)
                    mma16816(acc[mt][n], al[mt][0], al[mt][1], al[mt][2], al[mt][3], wh[n][0], wh[n][1]);
#pragma unroll
            for (int mt = 0; mt < 2; mt++)
#pragma unroll
                for (int n = 0; n < 4; n++)
                    mma16816(acc[mt][n], ah[mt][0], ah[mt][1], ah[mt][2], ah[mt][3], wl[n][0], wl[n][1]);
        }
        __syncthreads();
    }

    float* op = g_fpart + kz * (NB * 256);
#pragma unroll
    for (int mt = 0; mt < 2; mt++)
#pragma unroll
        for (int n = 0; n < 4; n++) {
            int row = bm + wm * 32 + mt * 16 + gr;
            int col = bn + wn * 32 + n * 8 + ct * 2;
            *(float2*)(op + row * 256 + col)       = make_float2(acc[mt][n][0], acc[mt][n][1]);
            *(float2*)(op + (row + 8) * 256 + col) = make_float2(acc[mt][n][2], acc[mt][n][3]);
        }
}

// ==================== quantum net + fused MLP head ====================
__global__ void quantum_k(const float* __restrict__ qp, const float* __restrict__ fb,
                          const float* __restrict__ p1w, const float* __restrict__ p1b,
                          const float* __restrict__ p2w, const float* __restrict__ p2b,
                          const float* __restrict__ p3w, const float* __restrict__ p3b,
                          float* __restrict__ out) {
    __shared__ float sc_[80], ss_[80];
    __shared__ float z1s[8][128];
    __shared__ float z2s[8][64];
    int tid = threadIdx.x;
    if (tid < 80) {
        float t = qp[tid] * 0.5f;
        ss_[tid] = sinf(t);
        sc_[tid] = cosf(t);
    }
    __syncthreads();
    int warp = tid >> 5, lane = tid & 31;
    int b = blockIdx.x * 8 + warp;

    float re[8], im[8];
    {
        float4 s0 = make_float4(0.f, 0.f, 0.f, 0.f), s1 = s0;
#pragma unroll
        for (int kz = 0; kz < FC_KSPLIT; kz++) {
            const float4* pp = (const float4*)(g_fpart + kz * (NB * 256) + b * 256 + lane * 8);
            float4 a = pp[0], c = pp[1];
            s0.x += a.x; s0.y += a.y; s0.z += a.z; s0.w += a.w;
            s1.x += c.x; s1.y += c.y; s1.z += c.z; s1.w += c.w;
        }
        const float4* bp = (const float4*)(fb + lane * 8);
        float4 b0 = bp[0], b1 = bp[1];
        re[0] = tanhf(s0.x + b0.x); re[1] = tanhf(s0.y + b0.y);
        re[2] = tanhf(s0.z + b0.z); re[3] = tanhf(s0.w + b0.w);
        re[4] = tanhf(s1.x + b1.x); re[5] = tanhf(s1.y + b1.y);
        re[6] = tanhf(s1.z + b1.z); re[7] = tanhf(s1.w + b1.w);
#pragma unroll
        for (int j = 0; j < 8; j++) im[j] = 0.f;
    }

    float s2 = 0.f;
#pragma unroll
    for (int j = 0; j < 8; j++) s2 += re[j] * re[j];
#pragma unroll
    for (int o = 16; o; o >>= 1) s2 += __shfl_xor_sync(0xffffffffu, s2, o);
    float inv = rsqrtf(s2);
#pragma unroll
    for (int j = 0; j < 8; j++) re[j] *= inv;

    const float R2 = 0.7071067811865476f;
#pragma unroll
    for (int w = 0; w < 5; w++) {
        int m = 16 >> w;
        float sgn = (lane & m) ? -1.f : 1.f;
#pragma unroll
        for (int j = 0; j < 8; j++) {
            float o_ = __shfl_xor_sync(0xffffffffu, re[j], m);
            re[j] = (sgn * re[j] + o_) * R2;
        }
    }
#pragma unroll
    for (int w = 5; w < 8; w++) {
        int mm = 1 << (7 - w);
#pragma unroll
        for (int j = 0; j < 8; j++) {
            if ((j & mm) == 0) {
                int j2 = j | mm;
                float a = re[j], bb = re[j2];
                re[j] = (a + bb) * R2;
                re[j2] = (a - bb) * R2;
            }
        }
    }

    float dre[8], dim_[8];
#pragma unroll
    for (int j = 0; j < 8; j++) {
        int a = lane * 8 + j;
        int k = (2 * __popc(a & 0xAA) + __popc(a & 0x55)) & 7;
        int par = __popc(a & (a >> 1) & 0x7F) & 1;
        float sn, cs;
        sincosf(0.78539816339744831f * (float)k, &sn, &cs);
        float sg = par ? -1.f : 1.f;
        dre[j] = sg * cs;
        dim_[j] = sg * sn;
    }

    for (int layer = 0; layer < 10; layer++) {
#pragma unroll
        for (int w = 0; w < 5; w++) {
            float c = sc_[layer * 8 + w], s = ss_[layer * 8 + w];
            int m = 16 >> w;
#pragma unroll
            for (int j = 0; j < 8; j++) {
                float pre = __shfl_xor_sync(0xffffffffu, re[j], m);
                float pim = __shfl_xor_sync(0xffffffffu, im[j], m);
                float nr = c * re[j] + s * pim;
                float ni = c * im[j] - s * pre;
                re[j] = nr;
                im[j] = ni;
            }
        }
#pragma unroll
        for (int w = 5; w < 8; w++) {
            float c = sc_[layer * 8 + w], s = ss_[layer * 8 + w];
            int mm = 1 << (7 - w);
#pragma unroll
            for (int j = 0; j < 8; j++) {
                if ((j & mm) == 0) {
                    int j2 = j | mm;
                    float r0 = re[j], i0 = im[j], r1 = re[j2], i1 = im[j2];
                    re[j]  = c * r0 + s * i1;  im[j]  = c * i0 - s * r1;
                    re[j2] = c * r1 + s * i0;  im[j2] = c * i1 - s * r0;
                }
            }
        }
#pragma unroll
        for (int j = 0; j < 8; j++) {
            float r = re[j], ii = im[j];
            re[j] = r * dre[j] - ii * dim_[j];
            im[j] = r * dim_[j] + ii * dre[j];
        }
    }

    float p[8], qv[8];
#pragma unroll
    for (int j = 0; j < 8; j++) p[j] = re[j] * re[j] + im[j] * im[j];
#pragma unroll
    for (int q = 0; q < 8; q++) {
        int bp = 7 - q;
        float s_ = 0.f;
#pragma unroll
        for (int j = 0; j < 8; j++) {
            int a = lane * 8 + j;
            s_ += ((a >> bp) & 1) ? -p[j] : p[j];
        }
#pragma unroll
        for (int o = 16; o; o >>= 1) s_ += __shfl_xor_sync(0xffffffffu, s_, o);
        qv[q] = s_;
    }

    // ---- fused MLP head, in-warp ----
#pragma unroll
    for (int r = 0; r < 4; r++) {
        int o = r * 32 + lane;
        float a = p1b[o];
#pragma unroll
        for (int k = 0; k < 8; k++) a += qv[k] * p1w[o * 8 + k];
        z1s[warp][o] = fmaxf(a, 0.f);
    }
    __syncwarp();
#pragma unroll
    for (int r = 0; r < 2; r++) {
        int o = r * 32 + lane;
        float a = p2b[o];
        const float* wrow = p2w + o * 128;
        const float* z = z1s[warp];
#pragma unroll 16
        for (int k = 0; k < 128; k++) a += z[k] * wrow[k];
        z2s[warp][o] = fmaxf(a, 0.f);
    }
    __syncwarp();
    if (lane < 10) {
        float a = p3b[lane];
        const float* wrow = p3w + lane * 64;
        const float* z = z2s[warp];
#pragma unroll
        for (int k = 0; k < 64; k++) a += z[k] * wrow[k];
        out[b * 10 + lane] = a;
    }
}

// ==================== launch ====================
extern "C" void kernel_launch(void* const* d_in, const int* in_sizes, int n_in,
                              void* d_out, int out_size) {
    (void)in_sizes; (void)n_in; (void)out_size;
    const float* x   = (const float*)d_in[0];
    const float* c1w = (const float*)d_in[1];
    const float* c1b = (const float*)d_in[2];
    const float* g1  = (const float*)d_in[3];
    const float* be1 = (const float*)d_in[4];
    const float* m1  = (const float*)d_in[5];
    const float* v1  = (const float*)d_in[6];
    const float* c2w = (const float*)d_in[7];
    const float* c2b = (const float*)d_in[8];
    const float* g2  = (const float*)d_in[9];
    const float* be2 = (const float*)d_in[10];
    const float* m2  = (const float*)d_in[11];
    const float* v2  = (const float*)d_in[12];
    const float* fw  = (const float*)d_in[13];
    const float* fb  = (const float*)d_in[14];
    const float* qp  = (const float*)d_in[15];
    const float* p1w = (const float*)d_in[16];
    const float* p1b = (const float*)d_in[17];
    const float* p2w = (const float*)d_in[18];
    const float* p2b = (const float*)d_in[19];
    const float* p3w = (const float*)d_in[20];
    const float* p3b = (const float*)d_in[21];
    float* out = (float*)d_out;

    cudaFuncSetAttribute(conv2mma_k, cudaFuncAttributeMaxDynamicSharedMemorySize, CV2_SMEM);

    repack_k<<<72, 256>>>(c2w, c2b, g2, be2, m2, v2);
    frepack_k<<<18, 256>>>();
    wrepack_k<<<784, 256>>>(fw);
    conv1_k<<<NB, 256>>>(x, c1w, c1b, g1, be1, m1, v1);
    conv2mma_k<<<NB, 256, CV2_SMEM>>>();
    dim3 fg(8, 4, FC_KSPLIT);
    fc_mma_k<<<fg, 256>>>();
    quantum_k<<<NB / 8, 256>>>(qp, fb, p1w, p1b, p2w, p2b, p3w, p3b, out);
}

// round 15
// speedup vs baseline: 1.1694x; 1.1694x over previous
#include <cuda_runtime.h>
#include <cuda_bf16.h>
#include <math.h>
#include <stdint.h>

#define NB 1024
#define FC_KSPLIT 14
#define FC_KC 224      // 3136 / 14

// -------- scratch (static __device__ globals; zero-initialized, no allocation) --------
__device__ __align__(16) __nv_bfloat16 g_p2h[NB * 3136];      // pool2 out bf16 hi (NCHW-flat)
__device__ __align__(16) __nv_bfloat16 g_p2l[NB * 3136];      // pool2 out bf16 lo
__device__ __align__(16) __nv_bfloat16 g_fwh[256 * 3136];     // fc weights bf16 hi
__device__ __align__(16) __nv_bfloat16 g_fwl[256 * 3136];     // fc weights bf16 lo
__device__ __align__(16) float g_fpart[FC_KSPLIT * NB * 256]; // FC split-K partials
__device__ __align__(16) __nv_bfloat16 g_w2bh[9 * 64 * 32];   // conv2 weights bf16 hi [pos][oc][ic]
__device__ __align__(16) __nv_bfloat16 g_w2bl[9 * 64 * 32];   // conv2 weights bf16 lo
__device__ float g_b2r[64];                                   // conv2 bias, BN-folded
__device__ float g_w1f[288];                                  // conv1 weights, BN-scaled
__device__ float g_b1f[32];                                   // conv1 bias, BN-folded

// ==================== warp-level bf16 HMMA + ldmatrix (baseline PTX) ====================
__device__ __forceinline__ void mma16816(float* c, uint32_t a0, uint32_t a1, uint32_t a2,
                                         uint32_t a3, uint32_t b0, uint32_t b1) {
    asm volatile(
        "mma.sync.aligned.m16n8k16.row.col.f32.bf16.bf16.f32 "
        "{%0,%1,%2,%3}, {%4,%5,%6,%7}, {%8,%9}, {%0,%1,%2,%3};"
        : "+f"(c[0]), "+f"(c[1]), "+f"(c[2]), "+f"(c[3])
        : "r"(a0), "r"(a1), "r"(a2), "r"(a3), "r"(b0), "r"(b1));
}
__device__ __forceinline__ void ldsm4(uint32_t* r, const __nv_bfloat16* p) {
    uint32_t a = (uint32_t)__cvta_generic_to_shared(p);
    asm volatile("ldmatrix.sync.aligned.m8n8.x4.shared.b16 {%0,%1,%2,%3}, [%4];"
                 : "=r"(r[0]), "=r"(r[1]), "=r"(r[2]), "=r"(r[3]) : "r"(a));
}
__device__ __forceinline__ uint2 hi2(float4 v) {
    __nv_bfloat16 h0 = __float2bfloat16(v.x), h1 = __float2bfloat16(v.y);
    __nv_bfloat16 h2 = __float2bfloat16(v.z), h3 = __float2bfloat16(v.w);
    return make_uint2((uint32_t)__bfloat16_as_ushort(h0) | ((uint32_t)__bfloat16_as_ushort(h1) << 16),
                      (uint32_t)__bfloat16_as_ushort(h2) | ((uint32_t)__bfloat16_as_ushort(h3) << 16));
}
__device__ __forceinline__ uint2 lo2(float4 v) {
    __nv_bfloat16 h0 = __float2bfloat16(v.x), h1 = __float2bfloat16(v.y);
    __nv_bfloat16 h2 = __float2bfloat16(v.z), h3 = __float2bfloat16(v.w);
    __nv_bfloat16 l0 = __float2bfloat16(v.x - __bfloat162float(h0));
    __nv_bfloat16 l1 = __float2bfloat16(v.y - __bfloat162float(h1));
    __nv_bfloat16 l2 = __float2bfloat16(v.z - __bfloat162float(h2));
    __nv_bfloat16 l3 = __float2bfloat16(v.w - __bfloat162float(h3));
    return make_uint2((uint32_t)__bfloat16_as_ushort(l0) | ((uint32_t)__bfloat16_as_ushort(l1) << 16),
                      (uint32_t)__bfloat16_as_ushort(l2) | ((uint32_t)__bfloat16_as_ushort(l3) << 16));
}

// ==================== weight repacks (conv2 BN-fold hi/lo, conv1 BN-fold, fc hi/lo) ====================
__global__ void repack_k(const float* __restrict__ w2, const float* __restrict__ b2,
                         const float* __restrict__ gm, const float* __restrict__ bt,
                         const float* __restrict__ mu, const float* __restrict__ vr,
                         const float* __restrict__ w1, const float* __restrict__ b1,
                         const float* __restrict__ gm1, const float* __restrict__ bt1,
                         const float* __restrict__ mu1, const float* __restrict__ vr1) {
    int i = blockIdx.x * blockDim.x + threadIdx.x;
    if (i < 64 * 32 * 9) {
        int oc = i / 288;
        int r  = i % 288;
        int ic = r / 9, k = r % 9;
        float sc = gm[oc] / sqrtf(vr[oc] + 1e-5f);
        float w = w2[i] * sc;
        __nv_bfloat16 h = __float2bfloat16(w);
        __nv_bfloat16 l = __float2bfloat16(w - __bfloat162float(h));
        g_w2bh[(k * 64 + oc) * 32 + ic] = h;
        g_w2bl[(k * 64 + oc) * 32 + ic] = l;
    }
    if (i < 64) {
        float sc = gm[i] / sqrtf(vr[i] + 1e-5f);
        g_b2r[i] = b2[i] * sc + bt[i] - mu[i] * sc;
    }
    if (i < 288) {
        int c = i / 9;
        float sc = gm1[c] / sqrtf(vr1[c] + 1e-5f);
        g_w1f[i] = w1[i] * sc;
    }
    if (i < 32) {
        float sc = gm1[i] / sqrtf(vr1[i] + 1e-5f);
        g_b1f[i] = b1[i] * sc + bt1[i] - mu1[i] * sc;
    }
}

__global__ void wrepack_k(const float* __restrict__ fw) {
    int i = blockIdx.x * blockDim.x + threadIdx.x;   // 200704 = 256*3136/4
    if (i < 200704) {
        float4 v = ((const float4*)fw)[i];
        *(uint2*)(g_fwh + i * 4) = hi2(v);
        *(uint2*)(g_fwl + i * 4) = lo2(v);
    }
}

// ==================== fused conv1 + conv2 (bf16 hi/lo 3-set implicit GEMM) ====================
// smem: bias | si[30][32] | sw1[288] | A-hi(290x40) | A-lo | B-hi(576x40)
// conv1 computed in-kernel straight into the A tile (rows 17..272 = image rows, halo zeroed).
#define A_STRIDE 40
#define OFF_SI   256
#define OFF_SW1  4096                               // 288 floats
#define OFF_AHI  5504
#define OFF_ALO  (OFF_AHI + 290 * A_STRIDE * 2)     // 28704
#define OFF_BHI  (OFF_ALO + 290 * A_STRIDE * 2)     // 51904
#define CV2_SMEM (OFF_BHI + 576 * A_STRIDE * 2)     // 97984

__global__ void __launch_bounds__(256, 2) conv2mma_k(const float* __restrict__ x) {
    extern __shared__ char smem[];
    int tid = threadIdx.x, wid = tid >> 5, lane = tid & 31;
    int b = blockIdx.x;
    float* sbias = (float*)smem;
    float (*si)[32] = (float(*)[32])(smem + OFF_SI);
    float* sw1 = (float*)(smem + OFF_SW1);
    __nv_bfloat16* sAh = (__nv_bfloat16*)(smem + OFF_AHI);
    __nv_bfloat16* sAl = (__nv_bfloat16*)(smem + OFF_ALO);
    __nv_bfloat16* sBh = (__nv_bfloat16*)(smem + OFF_BHI);

    if (tid < 64) sbias[tid] = g_b2r[tid];
    // zero conv1 input tile + A planes (halo + padding positions stay zero)
    for (int i = tid; i < 30 * 32; i += 256) ((float*)si)[i] = 0.f;
    for (int u = tid; u < 290 * 5; u += 256) {                 // 290 rows * 40 elem / 8
        *(uint4*)(sAh + u * 8) = make_uint4(0, 0, 0, 0);
        *(uint4*)(sAl + u * 8) = make_uint4(0, 0, 0, 0);
    }
    for (int i = tid; i < 288; i += 256) sw1[i] = g_w1f[i];
    __syncthreads();

    for (int i = tid; i < 784; i += 256) {
        int y = i / 28, xx = i % 28;
        si[y + 1][xx + 1] = x[b * 784 + i];
    }
    // stage B-hi (amortized across 8 warps), can overlap with conv1 below after sync
    __syncthreads();

    // ---- conv1 + bn + relu + maxpool -> A tile rows 17..272, bf16 hi/lo ----
    for (int idx = tid; idx < 32 * 196; idx += 256) {
        int c = idx & 31, pp = idx >> 5;
        int py = pp / 14, px = pp % 14;
        int iy = 2 * py, ix = 2 * px;
        float wk[9];
#pragma unroll
        for (int k = 0; k < 9; k++) wk[k] = sw1[c * 9 + k];
        float p[4][4];
#pragma unroll
        for (int r = 0; r < 4; r++)
#pragma unroll
            for (int cc = 0; cc < 4; cc++) p[r][cc] = si[iy + r][ix + cc];
        float v00 = 0.f, v01 = 0.f, v10 = 0.f, v11 = 0.f;
#pragma unroll
        for (int ky = 0; ky < 3; ky++)
#pragma unroll
            for (int kx = 0; kx < 3; kx++) {
                float w = wk[ky * 3 + kx];
                v00 += w * p[ky][kx];     v01 += w * p[ky][kx + 1];
                v10 += w * p[ky + 1][kx]; v11 += w * p[ky + 1][kx + 1];
            }
        float sh = sbias[0];  // placeholder to keep reg use low (overwritten below)
        sh = g_b1f[c];
        float m = fmaxf(fmaxf(v00, v01), fmaxf(v10, v11)) + sh;
        float v = fmaxf(m, 0.f);
        __nv_bfloat16 h = __float2bfloat16(v);
        __nv_bfloat16 l = __float2bfloat16(v - __bfloat162float(h));
        int row = (py + 1) * 16 + (px + 1) + 17;
        sAh[row * A_STRIDE + c] = h;
        sAl[row * A_STRIDE + c] = l;
    }
    for (int u = tid; u < 576 * 4; u += 256) {
        int row = u >> 2, c8 = u & 3;
        *(uint4*)(sBh + row * A_STRIDE + c8 * 8) = *(const uint4*)(g_w2bh + row * 32 + c8 * 8);
    }
    __syncthreads();

    int gr = lane >> 2, ct = lane & 3;
    int r_ = lane & 7, sel = lane >> 3;
    int a_roff = ((sel & 1) << 3) + r_;
    int a_koff = (sel >> 1) << 3;
    int b_noff = ((sel >> 1) << 3) + r_;
    int b_koff = (sel & 1) << 3;

    float acc[2][8][4];
#pragma unroll
    for (int mt = 0; mt < 2; mt++)
#pragma unroll
        for (int j = 0; j < 8; j++)
#pragma unroll
            for (int q = 0; q < 4; q++) acc[mt][j][q] = 0.f;

    int r0 = wid * 32;
#pragma unroll
    for (int pos = 0; pos < 9; pos++) {
        int ky = pos / 3, kx = pos % 3;
        int arow = r0 + (ky - 1) * 16 + (kx - 1) + 17;
#pragma unroll
        for (int s = 0; s < 2; s++) {
            int kb = s * 16;
            uint32_t ah[2][4], al[2][4], bh[4][4], bl[8][2];
#pragma unroll
            for (int j = 0; j < 8; j++) {            // LDG first (longest latency)
                const __nv_bfloat16* bp = g_w2bl + (pos * 64 + j * 8 + gr) * 32 + kb + ct * 2;
                bl[j][0] = *(const uint32_t*)bp;
                bl[j][1] = *(const uint32_t*)(bp + 8);
            }
#pragma unroll
            for (int mt = 0; mt < 2; mt++) {
                const __nv_bfloat16* pa = sAh + (arow + mt * 16 + a_roff) * A_STRIDE + kb + a_koff;
                ldsm4(ah[mt], pa);
                ldsm4(al[mt], pa + (OFF_ALO - OFF_AHI) / 2);
            }
#pragma unroll
            for (int jp = 0; jp < 4; jp++)
                ldsm4(bh[jp], sBh + (pos * 64 + jp * 16 + b_noff) * A_STRIDE + kb + b_koff);

            // pass-major MMA: each acc touched once per 16-MMA sweep (no RAW chains)
#pragma unroll
            for (int mt = 0; mt < 2; mt++)
#pragma unroll
                for (int j = 0; j < 8; j++)
                    mma16816(acc[mt][j], ah[mt][0], ah[mt][1], ah[mt][2], ah[mt][3],
                             bh[j >> 1][(j & 1) * 2], bh[j >> 1][(j & 1) * 2 + 1]);
#pragma unroll
            for (int mt = 0; mt < 2; mt++)
#pragma unroll
                for (int j = 0; j < 8; j++)
                    mma16816(acc[mt][j], ah[mt][0], ah[mt][1], ah[mt][2], ah[mt][3],
                             bl[j][0], bl[j][1]);
#pragma unroll
            for (int mt = 0; mt < 2; mt++)
#pragma unroll
                for (int j = 0; j < 8; j++)
                    mma16816(acc[mt][j], al[mt][0], al[mt][1], al[mt][2], al[mt][3],
                             bh[j >> 1][(j & 1) * 2], bh[j >> 1][(j & 1) * 2 + 1]);
        }
    }

    __syncthreads();
    float* D = (float*)(smem + OFF_AHI);
#pragma unroll
    for (int mt = 0; mt < 2; mt++)
#pragma unroll
        for (int j = 0; j < 8; j++) {
            int row = r0 + mt * 16 + gr;
            int col = j * 8 + ct * 2;
            *(float2*)(D + row * 68 + col)        = make_float2(acc[mt][j][0], acc[mt][j][1]);
            *(float2*)(D + (row + 8) * 68 + col)  = make_float2(acc[mt][j][2], acc[mt][j][3]);
        }
    __syncthreads();

    // epilogue: bias+relu+pool, write bf16 hi/lo (fc input) directly
    for (int idx = tid; idx < 64 * 49; idx += 256) {
        int oc = idx / 49, t = idx - oc * 49;
        int py = t / 7, px = t - py * 7;
        int s = (2 * py + 1) * 16 + (2 * px + 1);
        float v0 = D[s * 68 + oc];
        float v1 = D[(s + 1) * 68 + oc];
        float v2 = D[(s + 16) * 68 + oc];
        float v3 = D[(s + 17) * 68 + oc];
        float v = fmaxf(fmaxf(fmaxf(v0, v1), fmaxf(v2, v3)) + sbias[oc], 0.f);
        __nv_bfloat16 h = __float2bfloat16(v);
        __nv_bfloat16 l = __float2bfloat16(v - __bfloat162float(h));
        int o = b * 3136 + oc * 49 + t;
        g_p2h[o] = h;
        g_p2l[o] = l;
    }
}

// ==================== FC 3136 -> 256, split-K(14) bf16 hi/lo 3-pass HMMA (scalar frags) ====================
#define FCS 40
__global__ void __launch_bounds__(256) fc_mma_k() {
    __shared__ __nv_bfloat16 sAh[128 * FCS], sAl[128 * FCS];
    __shared__ __nv_bfloat16 sWh[64 * FCS],  sWl[64 * FCS];
    int tid = threadIdx.x, wid = tid >> 5, lane = tid & 31;
    int bm = blockIdx.x * 128, bn = blockIdx.y * 64, kz = blockIdx.z;
    int wm = wid & 3, wn = wid >> 2;
    int gr = lane >> 2, ct = lane & 3;

    float acc[2][4][4];
#pragma unroll
    for (int mt = 0; mt < 2; mt++)
#pragma unroll
        for (int n = 0; n < 4; n++)
#pragma unroll
            for (int q = 0; q < 4; q++) acc[mt][n][q] = 0.f;

    int k0 = kz * FC_KC;
    for (int kt = 0; kt < FC_KC / 32; kt++, k0 += 32) {
#pragma unroll
        for (int u = tid; u < 512; u += 256) {
            int row = u >> 2, c8 = u & 3;
            long g = (long)(bm + row) * 3136 + k0 + c8 * 8;
            *(uint4*)(sAh + row * FCS + c8 * 8) = *(const uint4*)(g_p2h + g);
            *(uint4*)(sAl + row * FCS + c8 * 8) = *(const uint4*)(g_p2l + g);
        }
#pragma unroll
        for (int u = tid; u < 256; u += 256) {
            int row = u >> 2, c8 = u & 3;
            long g = (long)(bn + row) * 3136 + k0 + c8 * 8;
            *(uint4*)(sWh + row * FCS + c8 * 8) = *(const uint4*)(g_fwh + g);
            *(uint4*)(sWl + row * FCS + c8 * 8) = *(const uint4*)(g_fwl + g);
        }
        __syncthreads();

#pragma unroll
        for (int s = 0; s < 2; s++) {
            int kb = s * 16;
            uint32_t ah[2][4], al[2][4], wh[4][2], wl[4][2];
#pragma unroll
            for (int mt = 0; mt < 2; mt++) {
                const __nv_bfloat16* p = sAh + (wm * 32 + mt * 16 + gr) * FCS + kb + ct * 2;
                ah[mt][0] = *(const uint32_t*)p;
                ah[mt][1] = *(const uint32_t*)(p + 8 * FCS);
                ah[mt][2] = *(const uint32_t*)(p + 8);
                ah[mt][3] = *(const uint32_t*)(p + 8 * FCS + 8);
                const __nv_bfloat16* q = sAl + (wm * 32 + mt * 16 + gr) * FCS + kb + ct * 2;
                al[mt][0] = *(const uint32_t*)q;
                al[mt][1] = *(const uint32_t*)(q + 8 * FCS);
                al[mt][2] = *(const uint32_t*)(q + 8);
                al[mt][3] = *(const uint32_t*)(q + 8 * FCS + 8);
            }
#pragma unroll
            for (int n = 0; n < 4; n++) {
                const __nv_bfloat16* p = sWh + (wn * 32 + n * 8 + gr) * FCS + kb + ct * 2;
                wh[n][0] = *(const uint32_t*)p;
                wh[n][1] = *(const uint32_t*)(p + 8);
                const __nv_bfloat16* q = sWl + (wn * 32 + n * 8 + gr) * FCS + kb + ct * 2;
                wl[n][0] = *(const uint32_t*)q;
                wl[n][1] = *(const uint32_t*)(q + 8);
            }
#pragma unroll
            for (int mt = 0; mt < 2; mt++)
#pragma unroll
                for (int n = 0; n < 4; n++)
                    mma16816(acc[mt][n], ah[mt][0], ah[mt][1], ah[mt][2], ah[mt][3], wh[n][0], wh[n][1]);
#pragma unroll
            for (int mt = 0; mt < 2; mt++)
#pragma unroll
                for (int n = 0; n < 4; n++)
                    mma16816(acc[mt][n], al[mt][0], al[mt][1], al[mt][2], al[mt][3], wh[n][0], wh[n][1]);
#pragma unroll
            for (int mt = 0; mt < 2; mt++)
#pragma unroll
                for (int n = 0; n < 4; n++)
                    mma16816(acc[mt][n], ah[mt][0], ah[mt][1], ah[mt][2], ah[mt][3], wl[n][0], wl[n][1]);
        }
        __syncthreads();
    }

    float* op = g_fpart + kz * (NB * 256);
#pragma unroll
    for (int mt = 0; mt < 2; mt++)
#pragma unroll
        for (int n = 0; n < 4; n++) {
            int row = bm + wm * 32 + mt * 16 + gr;
            int col = bn + wn * 32 + n * 8 + ct * 2;
            *(float2*)(op + row * 256 + col)       = make_float2(acc[mt][n][0], acc[mt][n][1]);
            *(float2*)(op + (row + 8) * 256 + col) = make_float2(acc[mt][n][2], acc[mt][n][3]);
        }
}

// ==================== quantum net + fused MLP head ====================
__global__ void quantum_k(const float* __restrict__ qp, const float* __restrict__ fb,
                          const float* __restrict__ p1w, const float* __restrict__ p1b,
                          const float* __restrict__ p2w, const float* __restrict__ p2b,
                          const float* __restrict__ p3w, const float* __restrict__ p3b,
                          float* __restrict__ out) {
    __shared__ float sc_[80], ss_[80];
    __shared__ float z1s[8][128];
    __shared__ float z2s[8][64];
    int tid = threadIdx.x;
    if (tid < 80) {
        float t = qp[tid] * 0.5f;
        ss_[tid] = sinf(t);
        sc_[tid] = cosf(t);
    }
    __syncthreads();
    int warp = tid >> 5, lane = tid & 31;
    int b = blockIdx.x * 8 + warp;

    float re[8], im[8];
    {
        float4 s0 = make_float4(0.f, 0.f, 0.f, 0.f), s1 = s0;
#pragma unroll
        for (int kz = 0; kz < FC_KSPLIT; kz++) {
            const float4* pp = (const float4*)(g_fpart + kz * (NB * 256) + b * 256 + lane * 8);
            float4 a = pp[0], c = pp[1];
            s0.x += a.x; s0.y += a.y; s0.z += a.z; s0.w += a.w;
            s1.x += c.x; s1.y += c.y; s1.z += c.z; s1.w += c.w;
        }
        const float4* bp = (const float4*)(fb + lane * 8);
        float4 b0 = bp[0], b1 = bp[1];
        re[0] = tanhf(s0.x + b0.x); re[1] = tanhf(s0.y + b0.y);
        re[2] = tanhf(s0.z + b0.z); re[3] = tanhf(s0.w + b0.w);
        re[4] = tanhf(s1.x + b1.x); re[5] = tanhf(s1.y + b1.y);
        re[6] = tanhf(s1.z + b1.z); re[7] = tanhf(s1.w + b1.w);
#pragma unroll
        for (int j = 0; j < 8; j++) im[j] = 0.f;
    }

    float s2 = 0.f;
#pragma unroll
    for (int j = 0; j < 8; j++) s2 += re[j] * re[j];
#pragma unroll
    for (int o = 16; o; o >>= 1) s2 += __shfl_xor_sync(0xffffffffu, s2, o);
    float inv = rsqrtf(s2);
#pragma unroll
    for (int j = 0; j < 8; j++) re[j] *= inv;

    const float R2 = 0.7071067811865476f;
#pragma unroll
    for (int w = 0; w < 5; w++) {
        int m = 16 >> w;
        float sgn = (lane & m) ? -1.f : 1.f;
#pragma unroll
        for (int j = 0; j < 8; j++) {
            float o_ = __shfl_xor_sync(0xffffffffu, re[j], m);
            re[j] = (sgn * re[j] + o_) * R2;
        }
    }
#pragma unroll
    for (int w = 5; w < 8; w++) {
        int mm = 1 << (7 - w);
#pragma unroll
        for (int j = 0; j < 8; j++) {
            if ((j & mm) == 0) {
                int j2 = j | mm;
                float a = re[j], bb = re[j2];
                re[j] = (a + bb) * R2;
                re[j2] = (a - bb) * R2;
            }
        }
    }

    float dre[8], dim_[8];
#pragma unroll
    for (int j = 0; j < 8; j++) {
        int a = lane * 8 + j;
        int k = (2 * __popc(a & 0xAA) + __popc(a & 0x55)) & 7;
        int par = __popc(a & (a >> 1) & 0x7F) & 1;
        float sn, cs;
        sincosf(0.78539816339744831f * (float)k, &sn, &cs);
        float sg = par ? -1.f : 1.f;
        dre[j] = sg * cs;
        dim_[j] = sg * sn;
    }

    for (int layer = 0; layer < 10; layer++) {
#pragma unroll
        for (int w = 0; w < 5; w++) {
            float c = sc_[layer * 8 + w], s = ss_[layer * 8 + w];
            int m = 16 >> w;
#pragma unroll
            for (int j = 0; j < 8; j++) {
                float pre = __shfl_xor_sync(0xffffffffu, re[j], m);
                float pim = __shfl_xor_sync(0xffffffffu, im[j], m);
                float nr = c * re[j] + s * pim;
                float ni = c * im[j] - s * pre;
                re[j] = nr;
                im[j] = ni;
            }
        }
#pragma unroll
        for (int w = 5; w < 8; w++) {
            float c = sc_[layer * 8 + w], s = ss_[layer * 8 + w];
            int mm = 1 << (7 - w);
#pragma unroll
            for (int j = 0; j < 8; j++) {
                if ((j & mm) == 0) {
                    int j2 = j | mm;
                    float r0 = re[j], i0 = im[j], r1 = re[j2], i1 = im[j2];
                    re[j]  = c * r0 + s * i1;  im[j]  = c * i0 - s * r1;
                    re[j2] = c * r1 + s * i0;  im[j2] = c * i1 - s * r0;
                }
            }
        }
#pragma unroll
        for (int j = 0; j < 8; j++) {
            float r = re[j], ii = im[j];
            re[j] = r * dre[j] - ii * dim_[j];
            im[j] = r * dim_[j] + ii * dre[j];
        }
    }

    float p[8], qv[8];
#pragma unroll
    for (int j = 0; j < 8; j++) p[j] = re[j] * re[j] + im[j] * im[j];
#pragma unroll
    for (int q = 0; q < 8; q++) {
        int bp = 7 - q;
        float s_ = 0.f;
#pragma unroll
        for (int j = 0; j < 8; j++) {
            int a = lane * 8 + j;
            s_ += ((a >> bp) & 1) ? -p[j] : p[j];
        }
#pragma unroll
        for (int o = 16; o; o >>= 1) s_ += __shfl_xor_sync(0xffffffffu, s_, o);
        qv[q] = s_;
    }

    // ---- fused MLP head, in-warp ----
#pragma unroll
    for (int r = 0; r < 4; r++) {
        int o = r * 32 + lane;
        float a = p1b[o];
#pragma unroll
        for (int k = 0; k < 8; k++) a += qv[k] * p1w[o * 8 + k];
        z1s[warp][o] = fmaxf(a, 0.f);
    }
    __syncwarp();
#pragma unroll
    for (int r = 0; r < 2; r++) {
        int o = r * 32 + lane;
        float a = p2b[o];
        const float* wrow = p2w + o * 128;
        const float* z = z1s[warp];
#pragma unroll 16
        for (int k = 0; k < 128; k++) a += z[k] * wrow[k];
        z2s[warp][o] = fmaxf(a, 0.f);
    }
    __syncwarp();
    if (lane < 10) {
        float a = p3b[lane];
        const float* wrow = p3w + lane * 64;
        const float* z = z2s[warp];
#pragma unroll
        for (int k = 0; k < 64; k++) a += z[k] * wrow[k];
        out[b * 10 + lane] = a;
    }
}

// ==================== launch ====================
extern "C" void kernel_launch(void* const* d_in, const int* in_sizes, int n_in,
                              void* d_out, int out_size) {
    (void)in_sizes; (void)n_in; (void)out_size;
    const float* x   = (const float*)d_in[0];
    const float* c1w = (const float*)d_in[1];
    const float* c1b = (const float*)d_in[2];
    const float* g1  = (const float*)d_in[3];
    const float* be1 = (const float*)d_in[4];
    const float* m1  = (const float*)d_in[5];
    const float* v1  = (const float*)d_in[6];
    const float* c2w = (const float*)d_in[7];
    const float* c2b = (const float*)d_in[8];
    const float* g2  = (const float*)d_in[9];
    const float* be2 = (const float*)d_in[10];
    const float* m2  = (const float*)d_in[11];
    const float* v2  = (const float*)d_in[12];
    const float* fw  = (const float*)d_in[13];
    const float* fb  = (const float*)d_in[14];
    const float* qp  = (const float*)d_in[15];
    const float* p1w = (const float*)d_in[16];
    const float* p1b = (const float*)d_in[17];
    const float* p2w = (const float*)d_in[18];
    const float* p2b = (const float*)d_in[19];
    const float* p3w = (const float*)d_in[20];
    const float* p3b = (const float*)d_in[21];
    float* out = (float*)d_out;

    cudaFuncSetAttribute(conv2mma_k, cudaFuncAttributeMaxDynamicSharedMemorySize, CV2_SMEM);

    repack_k<<<72, 256>>>(c2w, c2b, g2, be2, m2, v2, c1w, c1b, g1, be1, m1, v1);
    wrepack_k<<<784, 256>>>(fw);
    conv2mma_k<<<NB, 256, CV2_SMEM>>>(x);
    dim3 fg(8, 4, FC_KSPLIT);
    fc_mma_k<<<fg, 256>>>();
    quantum_k<<<NB / 8, 256>>>(qp, fb, p1w, p1b, p2w, p2b, p3w, p3b, out);
}

// round 16
// speedup vs baseline: 1.4734x; 1.2599x over previous
#include <cuda_runtime.h>
#include <cuda_bf16.h>
#include <cuda_fp16.h>
#include <math.h>
#include <stdint.h>

#define NB 1024
#define FC_KSPLIT 14
#define FC_KC 224      // 3136 / 14

// -------- scratch (static __device__ globals; zero-initialized, no allocation) --------
__device__ __align__(16) __nv_bfloat16 g_p2h[NB * 3136];      // pool2 out bf16 hi (NCHW-flat)
__device__ __align__(16) __nv_bfloat16 g_p2l[NB * 3136];      // pool2 out bf16 lo
__device__ __align__(16) __nv_bfloat16 g_fwh[256 * 3136];     // fc weights bf16 hi
__device__ __align__(16) __nv_bfloat16 g_fwl[256 * 3136];     // fc weights bf16 lo
__device__ __align__(16) float g_fpart[FC_KSPLIT * NB * 256]; // FC split-K partials
__device__ __align__(16) __half g_w2f[9 * 64 * 32];           // conv2 weights fp16 [pos][oc][ic]
__device__ float g_b2r[64];                                   // conv2 bias, BN-folded
__device__ float g_w1f[288];                                  // conv1 weights, BN-scaled
__device__ float g_b1f[32];                                   // conv1 bias, BN-folded

// ==================== warp-level HMMA + ldmatrix (baseline PTX) ====================
__device__ __forceinline__ void mma16816bf(float* c, uint32_t a0, uint32_t a1, uint32_t a2,
                                           uint32_t a3, uint32_t b0, uint32_t b1) {
    asm volatile(
        "mma.sync.aligned.m16n8k16.row.col.f32.bf16.bf16.f32 "
        "{%0,%1,%2,%3}, {%4,%5,%6,%7}, {%8,%9}, {%0,%1,%2,%3};"
        : "+f"(c[0]), "+f"(c[1]), "+f"(c[2]), "+f"(c[3])
        : "r"(a0), "r"(a1), "r"(a2), "r"(a3), "r"(b0), "r"(b1));
}
__device__ __forceinline__ void mma16816h(float* c, uint32_t a0, uint32_t a1, uint32_t a2,
                                          uint32_t a3, uint32_t b0, uint32_t b1) {
    asm volatile(
        "mma.sync.aligned.m16n8k16.row.col.f32.f16.f16.f32 "
        "{%0,%1,%2,%3}, {%4,%5,%6,%7}, {%8,%9}, {%0,%1,%2,%3};"
        : "+f"(c[0]), "+f"(c[1]), "+f"(c[2]), "+f"(c[3])
        : "r"(a0), "r"(a1), "r"(a2), "r"(a3), "r"(b0), "r"(b1));
}
__device__ __forceinline__ void ldsm4h(uint32_t* r, const __half* p) {
    uint32_t a = (uint32_t)__cvta_generic_to_shared(p);
    asm volatile("ldmatrix.sync.aligned.m8n8.x4.shared.b16 {%0,%1,%2,%3}, [%4];"
                 : "=r"(r[0]), "=r"(r[1]), "=r"(r[2]), "=r"(r[3]) : "r"(a));
}
__device__ __forceinline__ uint2 hi2(float4 v) {
    __nv_bfloat16 h0 = __float2bfloat16(v.x), h1 = __float2bfloat16(v.y);
    __nv_bfloat16 h2 = __float2bfloat16(v.z), h3 = __float2bfloat16(v.w);
    return make_uint2((uint32_t)__bfloat16_as_ushort(h0) | ((uint32_t)__bfloat16_as_ushort(h1) << 16),
                      (uint32_t)__bfloat16_as_ushort(h2) | ((uint32_t)__bfloat16_as_ushort(h3) << 16));
}
__device__ __forceinline__ uint2 lo2(float4 v) {
    __nv_bfloat16 h0 = __float2bfloat16(v.x), h1 = __float2bfloat16(v.y);
    __nv_bfloat16 h2 = __float2bfloat16(v.z), h3 = __float2bfloat16(v.w);
    __nv_bfloat16 l0 = __float2bfloat16(v.x - __bfloat162float(h0));
    __nv_bfloat16 l1 = __float2bfloat16(v.y - __bfloat162float(h1));
    __nv_bfloat16 l2 = __float2bfloat16(v.z - __bfloat162float(h2));
    __nv_bfloat16 l3 = __float2bfloat16(v.w - __bfloat162float(h3));
    return make_uint2((uint32_t)__bfloat16_as_ushort(l0) | ((uint32_t)__bfloat16_as_ushort(l1) << 16),
                      (uint32_t)__bfloat16_as_ushort(l2) | ((uint32_t)__bfloat16_as_ushort(l3) << 16));
}

// ==================== weight repacks ====================
__global__ void repack_k(const float* __restrict__ w2, const float* __restrict__ b2,
                         const float* __restrict__ gm, const float* __restrict__ bt,
                         const float* __restrict__ mu, const float* __restrict__ vr,
                         const float* __restrict__ w1, const float* __restrict__ b1,
                         const float* __restrict__ gm1, const float* __restrict__ bt1,
                         const float* __restrict__ mu1, const float* __restrict__ vr1) {
    int i = blockIdx.x * blockDim.x + threadIdx.x;
    if (i < 64 * 32 * 9) {
        int oc = i / 288;
        int r  = i % 288;
        int ic = r / 9, k = r % 9;
        float sc = gm[oc] / sqrtf(vr[oc] + 1e-5f);
        g_w2f[(k * 64 + oc) * 32 + ic] = __float2half(w2[i] * sc);
    }
    if (i < 64) {
        float sc = gm[i] / sqrtf(vr[i] + 1e-5f);
        g_b2r[i] = b2[i] * sc + bt[i] - mu[i] * sc;
    }
    if (i < 288) {
        int c = i / 9;
        float sc = gm1[c] / sqrtf(vr1[c] + 1e-5f);
        g_w1f[i] = w1[i] * sc;
    }
    if (i < 32) {
        float sc = gm1[i] / sqrtf(vr1[i] + 1e-5f);
        g_b1f[i] = b1[i] * sc + bt1[i] - mu1[i] * sc;
    }
}

__global__ void wrepack_k(const float* __restrict__ fw) {
    int i = blockIdx.x * blockDim.x + threadIdx.x;   // 200704 = 256*3136/4
    if (i < 200704) {
        float4 v = ((const float4*)fw)[i];
        *(uint2*)(g_fwh + i * 4) = hi2(v);
        *(uint2*)(g_fwl + i * 4) = lo2(v);
    }
}

// ==================== fused conv1 + conv2 (fp16 single-pass implicit GEMM) ====================
// smem: bias | si[30][32] | sw1[288] | A(290x40 fp16) | B(576x40 fp16)
#define A_STRIDE 40
#define OFF_SI   256
#define OFF_SW1  4096
#define OFF_A    5504
#define OFF_B    (OFF_A + 290 * A_STRIDE * 2)       // 28704
#define CV2_SMEM 75136                              // max(staging end 74784, D epi 5504+69632)

__global__ void __launch_bounds__(256, 2) conv2mma_k(const float* __restrict__ x) {
    extern __shared__ char smem[];
    int tid = threadIdx.x, wid = tid >> 5, lane = tid & 31;
    int b = blockIdx.x;
    float* sbias = (float*)smem;
    float (*si)[32] = (float(*)[32])(smem + OFF_SI);
    float* sw1 = (float*)(smem + OFF_SW1);
    __half* sA = (__half*)(smem + OFF_A);
    __half* sB = (__half*)(smem + OFF_B);

    if (tid < 64) sbias[tid] = g_b2r[tid];
    for (int i = tid; i < 30 * 32; i += 256) ((float*)si)[i] = 0.f;
    for (int u = tid; u < 290 * 5; u += 256)                   // zero A plane (halo stays 0)
        *(uint4*)(sA + u * 8) = make_uint4(0, 0, 0, 0);
    for (int i = tid; i < 288; i += 256) sw1[i] = g_w1f[i];
    __syncthreads();

    for (int i = tid; i < 784; i += 256) {
        int y = i / 28, xx = i % 28;
        si[y + 1][xx + 1] = x[b * 784 + i];
    }
    __syncthreads();

    // ---- conv1 + bn + relu + maxpool -> A tile (fp16) ----
    for (int idx = tid; idx < 32 * 196; idx += 256) {
        int c = idx & 31, pp = idx >> 5;
        int py = pp / 14, px = pp % 14;
        int iy = 2 * py, ix = 2 * px;
        float wk[9];
#pragma unroll
        for (int k = 0; k < 9; k++) wk[k] = sw1[c * 9 + k];
        float p[4][4];
#pragma unroll
        for (int r = 0; r < 4; r++)
#pragma unroll
            for (int cc = 0; cc < 4; cc++) p[r][cc] = si[iy + r][ix + cc];
        float v00 = 0.f, v01 = 0.f, v10 = 0.f, v11 = 0.f;
#pragma unroll
        for (int ky = 0; ky < 3; ky++)
#pragma unroll
            for (int kx = 0; kx < 3; kx++) {
                float w = wk[ky * 3 + kx];
                v00 += w * p[ky][kx];     v01 += w * p[ky][kx + 1];
                v10 += w * p[ky + 1][kx]; v11 += w * p[ky + 1][kx + 1];
            }
        float m = fmaxf(fmaxf(v00, v01), fmaxf(v10, v11)) + g_b1f[c];
        float v = fmaxf(m, 0.f);
        int row = (py + 1) * 16 + (px + 1) + 17;
        sA[row * A_STRIDE + c] = __float2half(v);
    }
    for (int u = tid; u < 576 * 4; u += 256) {
        int row = u >> 2, c8 = u & 3;
        *(uint4*)(sB + row * A_STRIDE + c8 * 8) = *(const uint4*)(g_w2f + row * 32 + c8 * 8);
    }
    __syncthreads();

    int gr = lane >> 2, ct = lane & 3;
    int r_ = lane & 7, sel = lane >> 3;
    int a_roff = ((sel & 1) << 3) + r_;
    int a_koff = (sel >> 1) << 3;
    int b_noff = ((sel >> 1) << 3) + r_;
    int b_koff = (sel & 1) << 3;

    float acc[2][8][4];
#pragma unroll
    for (int mt = 0; mt < 2; mt++)
#pragma unroll
        for (int j = 0; j < 8; j++)
#pragma unroll
            for (int q = 0; q < 4; q++) acc[mt][j][q] = 0.f;

    int r0 = wid * 32;
#pragma unroll
    for (int pos = 0; pos < 9; pos++) {
        int ky = pos / 3, kx = pos % 3;
        int arow = r0 + (ky - 1) * 16 + (kx - 1) + 17;
#pragma unroll
        for (int s = 0; s < 2; s++) {
            int kb = s * 16;
            uint32_t ah[2][4], bh[4][4];
#pragma unroll
            for (int mt = 0; mt < 2; mt++)
                ldsm4h(ah[mt], sA + (arow + mt * 16 + a_roff) * A_STRIDE + kb + a_koff);
#pragma unroll
            for (int jp = 0; jp < 4; jp++)
                ldsm4h(bh[jp], sB + (pos * 64 + jp * 16 + b_noff) * A_STRIDE + kb + b_koff);
#pragma unroll
            for (int mt = 0; mt < 2; mt++)
#pragma unroll
                for (int j = 0; j < 8; j++)
                    mma16816h(acc[mt][j], ah[mt][0], ah[mt][1], ah[mt][2], ah[mt][3],
                              bh[j >> 1][(j & 1) * 2], bh[j >> 1][(j & 1) * 2 + 1]);
        }
    }

    __syncthreads();
    float* D = (float*)(smem + OFF_A);
#pragma unroll
    for (int mt = 0; mt < 2; mt++)
#pragma unroll
        for (int j = 0; j < 8; j++) {
            int row = r0 + mt * 16 + gr;
            int col = j * 8 + ct * 2;
            *(float2*)(D + row * 68 + col)        = make_float2(acc[mt][j][0], acc[mt][j][1]);
            *(float2*)(D + (row + 8) * 68 + col)  = make_float2(acc[mt][j][2], acc[mt][j][3]);
        }
    __syncthreads();

    // epilogue: bias+relu+pool, write bf16 hi/lo (fc input)
    for (int idx = tid; idx < 64 * 49; idx += 256) {
        int oc = idx / 49, t = idx - oc * 49;
        int py = t / 7, px = t - py * 7;
        int s = (2 * py + 1) * 16 + (2 * px + 1);
        float v0 = D[s * 68 + oc];
        float v1 = D[(s + 1) * 68 + oc];
        float v2 = D[(s + 16) * 68 + oc];
        float v3 = D[(s + 17) * 68 + oc];
        float v = fmaxf(fmaxf(fmaxf(v0, v1), fmaxf(v2, v3)) + sbias[oc], 0.f);
        __nv_bfloat16 h = __float2bfloat16(v);
        __nv_bfloat16 l = __float2bfloat16(v - __bfloat162float(h));
        int o = b * 3136 + oc * 49 + t;
        g_p2h[o] = h;
        g_p2l[o] = l;
    }
}

// ==================== FC 3136 -> 256, split-K(14) bf16 hi/lo 3-pass HMMA (scalar frags) ====================
#define FCS 40
__global__ void __launch_bounds__(256) fc_mma_k() {
    __shared__ __nv_bfloat16 sAh[128 * FCS], sAl[128 * FCS];
    __shared__ __nv_bfloat16 sWh[64 * FCS],  sWl[64 * FCS];
    int tid = threadIdx.x, wid = tid >> 5, lane = tid & 31;
    int bm = blockIdx.x * 128, bn = blockIdx.y * 64, kz = blockIdx.z;
    int wm = wid & 3, wn = wid >> 2;
    int gr = lane >> 2, ct = lane & 3;

    float acc[2][4][4];
#pragma unroll
    for (int mt = 0; mt < 2; mt++)
#pragma unroll
        for (int n = 0; n < 4; n++)
#pragma unroll
            for (int q = 0; q < 4; q++) acc[mt][n][q] = 0.f;

    int k0 = kz * FC_KC;
    for (int kt = 0; kt < FC_KC / 32; kt++, k0 += 32) {
#pragma unroll
        for (int u = tid; u < 512; u += 256) {
            int row = u >> 2, c8 = u & 3;
            long g = (long)(bm + row) * 3136 + k0 + c8 * 8;
            *(uint4*)(sAh + row * FCS + c8 * 8) = *(const uint4*)(g_p2h + g);
            *(uint4*)(sAl + row * FCS + c8 * 8) = *(const uint4*)(g_p2l + g);
        }
#pragma unroll
        for (int u = tid; u < 256; u += 256) {
            int row = u >> 2, c8 = u & 3;
            long g = (long)(bn + row) * 3136 + k0 + c8 * 8;
            *(uint4*)(sWh + row * FCS + c8 * 8) = *(const uint4*)(g_fwh + g);
            *(uint4*)(sWl + row * FCS + c8 * 8) = *(const uint4*)(g_fwl + g);
        }
        __syncthreads();

#pragma unroll
        for (int s = 0; s < 2; s++) {
            int kb = s * 16;
            uint32_t ah[2][4], al[2][4], wh[4][2], wl[4][2];
#pragma unroll
            for (int mt = 0; mt < 2; mt++) {
                const __nv_bfloat16* p = sAh + (wm * 32 + mt * 16 + gr) * FCS + kb + ct * 2;
                ah[mt][0] = *(const uint32_t*)p;
                ah[mt][1] = *(const uint32_t*)(p + 8 * FCS);
                ah[mt][2] = *(const uint32_t*)(p + 8);
                ah[mt][3] = *(const uint32_t*)(p + 8 * FCS + 8);
                const __nv_bfloat16* q = sAl + (wm * 32 + mt * 16 + gr) * FCS + kb + ct * 2;
                al[mt][0] = *(const uint32_t*)q;
                al[mt][1] = *(const uint32_t*)(q + 8 * FCS);
                al[mt][2] = *(const uint32_t*)(q + 8);
                al[mt][3] = *(const uint32_t*)(q + 8 * FCS + 8);
            }
#pragma unroll
            for (int n = 0; n < 4; n++) {
                const __nv_bfloat16* p = sWh + (wn * 32 + n * 8 + gr) * FCS + kb + ct * 2;
                wh[n][0] = *(const uint32_t*)p;
                wh[n][1] = *(const uint32_t*)(p + 8);
                const __nv_bfloat16* q = sWl + (wn * 32 + n * 8 + gr) * FCS + kb + ct * 2;
                wl[n][0] = *(const uint32_t*)q;
                wl[n][1] = *(const uint32_t*)(q + 8);
            }
#pragma unroll
            for (int mt = 0; mt < 2; mt++)
#pragma unroll
                for (int n = 0; n < 4; n++)
                    mma16816bf(acc[mt][n], ah[mt][0], ah[mt][1], ah[mt][2], ah[mt][3], wh[n][0], wh[n][1]);
#pragma unroll
            for (int mt = 0; mt < 2; mt++)
#pragma unroll
                for (int n = 0; n < 4; n++)
                    mma16816bf(acc[mt][n], al[mt][0], al[mt][1], al[mt][2], al[mt][3], wh[n][0], wh[n][1]);
#pragma unroll
            for (int mt = 0; mt < 2; mt++)
#pragma unroll
                for (int n = 0; n < 4; n++)
                    mma16816bf(acc[mt][n], ah[mt][0], ah[mt][1], ah[mt][2], ah[mt][3], wl[n][0], wl[n][1]);
        }
        __syncthreads();
    }

    float* op = g_fpart + kz * (NB * 256);
#pragma unroll
    for (int mt = 0; mt < 2; mt++)
#pragma unroll
        for (int n = 0; n < 4; n++) {
            int row = bm + wm * 32 + mt * 16 + gr;
            int col = bn + wn * 32 + n * 8 + ct * 2;
            *(float2*)(op + row * 256 + col)       = make_float2(acc[mt][n][0], acc[mt][n][1]);
            *(float2*)(op + (row + 8) * 256 + col) = make_float2(acc[mt][n][2], acc[mt][n][3]);
        }
}

// ==================== quantum net + fused MLP head ====================
__global__ void quantum_k(const float* __restrict__ qp, const float* __restrict__ fb,
                          const float* __restrict__ p1w, const float* __restrict__ p1b,
                          const float* __restrict__ p2w, const float* __restrict__ p2b,
                          const float* __restrict__ p3w, const float* __restrict__ p3b,
                          float* __restrict__ out) {
    __shared__ float sc_[80], ss_[80];
    __shared__ float z1s[8][128];
    __shared__ float z2s[8][64];
    int tid = threadIdx.x;
    if (tid < 80) {
        float t = qp[tid] * 0.5f;
        ss_[tid] = sinf(t);
        sc_[tid] = cosf(t);
    }
    __syncthreads();
    int warp = tid >> 5, lane = tid & 31;
    int b = blockIdx.x * 8 + warp;

    float re[8], im[8];
    {
        float4 s0 = make_float4(0.f, 0.f, 0.f, 0.f), s1 = s0;
#pragma unroll
        for (int kz = 0; kz < FC_KSPLIT; kz++) {
            const float4* pp = (const float4*)(g_fpart + kz * (NB * 256) + b * 256 + lane * 8);
            float4 a = pp[0], c = pp[1];
            s0.x += a.x; s0.y += a.y; s0.z += a.z; s0.w += a.w;
            s1.x += c.x; s1.y += c.y; s1.z += c.z; s1.w += c.w;
        }
        const float4* bp = (const float4*)(fb + lane * 8);
        float4 b0 = bp[0], b1 = bp[1];
        re[0] = tanhf(s0.x + b0.x); re[1] = tanhf(s0.y + b0.y);
        re[2] = tanhf(s0.z + b0.z); re[3] = tanhf(s0.w + b0.w);
        re[4] = tanhf(s1.x + b1.x); re[5] = tanhf(s1.y + b1.y);
        re[6] = tanhf(s1.z + b1.z); re[7] = tanhf(s1.w + b1.w);
#pragma unroll
        for (int j = 0; j < 8; j++) im[j] = 0.f;
    }

    float s2 = 0.f;
#pragma unroll
    for (int j = 0; j < 8; j++) s2 += re[j] * re[j];
#pragma unroll
    for (int o = 16; o; o >>= 1) s2 += __shfl_xor_sync(0xffffffffu, s2, o);
    float inv = rsqrtf(s2);
#pragma unroll
    for (int j = 0; j < 8; j++) re[j] *= inv;

    const float R2 = 0.7071067811865476f;
#pragma unroll
    for (int w = 0; w < 5; w++) {
        int m = 16 >> w;
        float sgn = (lane & m) ? -1.f : 1.f;
#pragma unroll
        for (int j = 0; j < 8; j++) {
            float o_ = __shfl_xor_sync(0xffffffffu, re[j], m);
            re[j] = (sgn * re[j] + o_) * R2;
        }
    }
#pragma unroll
    for (int w = 5; w < 8; w++) {
        int mm = 1 << (7 - w);
#pragma unroll
        for (int j = 0; j < 8; j++) {
            if ((j & mm) == 0) {
                int j2 = j | mm;
                float a = re[j], bb = re[j2];
                re[j] = (a + bb) * R2;
                re[j2] = (a - bb) * R2;
            }
        }
    }

    float dre[8], dim_[8];
#pragma unroll
    for (int j = 0; j < 8; j++) {
        int a = lane * 8 + j;
        int k = (2 * __popc(a & 0xAA) + __popc(a & 0x55)) & 7;
        int par = __popc(a & (a >> 1) & 0x7F) & 1;
        float sn, cs;
        sincosf(0.78539816339744831f * (float)k, &sn, &cs);
        float sg = par ? -1.f : 1.f;
        dre[j] = sg * cs;
        dim_[j] = sg * sn;
    }

    for (int layer = 0; layer < 10; layer++) {
#pragma unroll
        for (int w = 0; w < 5; w++) {
            float c = sc_[layer * 8 + w], s = ss_[layer * 8 + w];
            int m = 16 >> w;
#pragma unroll
            for (int j = 0; j < 8; j++) {
                float pre = __shfl_xor_sync(0xffffffffu, re[j], m);
                float pim = __shfl_xor_sync(0xffffffffu, im[j], m);
                float nr = c * re[j] + s * pim;
                float ni = c * im[j] - s * pre;
                re[j] = nr;
                im[j] = ni;
            }
        }
#pragma unroll
        for (int w = 5; w < 8; w++) {
            float c = sc_[layer * 8 + w], s = ss_[layer * 8 + w];
            int mm = 1 << (7 - w);
#pragma unroll
            for (int j = 0; j < 8; j++) {
                if ((j & mm) == 0) {
                    int j2 = j | mm;
                    float r0 = re[j], i0 = im[j], r1 = re[j2], i1 = im[j2];
                    re[j]  = c * r0 + s * i1;  im[j]  = c * i0 - s * r1;
                    re[j2] = c * r1 + s * i0;  im[j2] = c * i1 - s * r0;
                }
            }
        }
#pragma unroll
        for (int j = 0; j < 8; j++) {
            float r = re[j], ii = im[j];
            re[j] = r * dre[j] - ii * dim_[j];
            im[j] = r * dim_[j] + ii * dre[j];
        }
    }

    float p[8], qv[8];
#pragma unroll
    for (int j = 0; j < 8; j++) p[j] = re[j] * re[j] + im[j] * im[j];
#pragma unroll
    for (int q = 0; q < 8; q++) {
        int bp = 7 - q;
        float s_ = 0.f;
#pragma unroll
        for (int j = 0; j < 8; j++) {
            int a = lane * 8 + j;
            s_ += ((a >> bp) & 1) ? -p[j] : p[j];
        }
#pragma unroll
        for (int o = 16; o; o >>= 1) s_ += __shfl_xor_sync(0xffffffffu, s_, o);
        qv[q] = s_;
    }

    // ---- fused MLP head, in-warp ----
#pragma unroll
    for (int r = 0; r < 4; r++) {
        int o = r * 32 + lane;
        float a = p1b[o];
#pragma unroll
        for (int k = 0; k < 8; k++) a += qv[k] * p1w[o * 8 + k];
        z1s[warp][o] = fmaxf(a, 0.f);
    }
    __syncwarp();
#pragma unroll
    for (int r = 0; r < 2; r++) {
        int o = r * 32 + lane;
        float a = p2b[o];
        const float* wrow = p2w + o * 128;
        const float* z = z1s[warp];
#pragma unroll 16
        for (int k = 0; k < 128; k++) a += z[k] * wrow[k];
        z2s[warp][o] = fmaxf(a, 0.f);
    }
    __syncwarp();
    if (lane < 10) {
        float a = p3b[lane];
        const float* wrow = p3w + lane * 64;
        const float* z = z2s[warp];
#pragma unroll
        for (int k = 0; k < 64; k++) a += z[k] * wrow[k];
        out[b * 10 + lane] = a;
    }
}

// ==================== launch ====================
extern "C" void kernel_launch(void* const* d_in, const int* in_sizes, int n_in,
                              void* d_out, int out_size) {
    (void)in_sizes; (void)n_in; (void)out_size;
    const float* x   = (const float*)d_in[0];
    const float* c1w = (const float*)d_in[1];
    const float* c1b = (const float*)d_in[2];
    const float* g1  = (const float*)d_in[3];
    const float* be1 = (const float*)d_in[4];
    const float* m1  = (const float*)d_in[5];
    const float* v1  = (const float*)d_in[6];
    const float* c2w = (const float*)d_in[7];
    const float* c2b = (const float*)d_in[8];
    const float* g2  = (const float*)d_in[9];
    const float* be2 = (const float*)d_in[10];
    const float* m2  = (const float*)d_in[11];
    const float* v2  = (const float*)d_in[12];
    const float* fw  = (const float*)d_in[13];
    const float* fb  = (const float*)d_in[14];
    const float* qp  = (const float*)d_in[15];
    const float* p1w = (const float*)d_in[16];
    const float* p1b = (const float*)d_in[17];
    const float* p2w = (const float*)d_in[18];
    const float* p2b = (const float*)d_in[19];
    const float* p3w = (const float*)d_in[20];
    const float* p3b = (const float*)d_in[21];
    float* out = (float*)d_out;

    cudaFuncSetAttribute(conv2mma_k, cudaFuncAttributeMaxDynamicSharedMemorySize, CV2_SMEM);

    repack_k<<<72, 256>>>(c2w, c2b, g2, be2, m2, v2, c1w, c1b, g1, be1, m1, v1);
    wrepack_k<<<784, 256>>>(fw);
    conv2mma_k<<<NB, 256, CV2_SMEM>>>(x);
    dim3 fg(8, 4, FC_KSPLIT);
    fc_mma_k<<<fg, 256>>>();
    quantum_k<<<NB / 8, 256>>>(qp, fb, p1w, p1b, p2w, p2b, p3w, p3b, out);
}

// round 17
// speedup vs baseline: 1.6758x; 1.1374x over previous
#include <cuda_runtime.h>
#include <cuda_bf16.h>
#include <cuda_fp16.h>
#include <math.h>
#include <stdint.h>

#define NB 1024
#define FC_KSPLIT 14
#define FC_KC 224      // 3136 / 14

// -------- scratch (static __device__ globals; zero-initialized, no allocation) --------
__device__ __align__(16) __half g_p2f[NB * 3136];             // pool2 out fp16 (NCHW-flat)
__device__ __align__(16) __half g_fwf[256 * 3136];            // fc weights fp16
__device__ __align__(16) float g_fpart[FC_KSPLIT * NB * 256]; // FC split-K partials
__device__ __align__(16) __half g_w2f[9 * 64 * 32];           // conv2 weights fp16 [pos][oc][ic]
__device__ float g_b2r[64];                                   // conv2 bias, BN-folded
__device__ float g_w1f[288];                                  // conv1 weights, BN-scaled
__device__ float g_b1f[32];                                   // conv1 bias, BN-folded

// ==================== warp-level HMMA + ldmatrix (baseline PTX) ====================
__device__ __forceinline__ void mma16816h(float* c, uint32_t a0, uint32_t a1, uint32_t a2,
                                          uint32_t a3, uint32_t b0, uint32_t b1) {
    asm volatile(
        "mma.sync.aligned.m16n8k16.row.col.f32.f16.f16.f32 "
        "{%0,%1,%2,%3}, {%4,%5,%6,%7}, {%8,%9}, {%0,%1,%2,%3};"
        : "+f"(c[0]), "+f"(c[1]), "+f"(c[2]), "+f"(c[3])
        : "r"(a0), "r"(a1), "r"(a2), "r"(a3), "r"(b0), "r"(b1));
}
__device__ __forceinline__ void ldsm4h(uint32_t* r, const __half* p) {
    uint32_t a = (uint32_t)__cvta_generic_to_shared(p);
    asm volatile("ldmatrix.sync.aligned.m8n8.x4.shared.b16 {%0,%1,%2,%3}, [%4];"
                 : "=r"(r[0]), "=r"(r[1]), "=r"(r[2]), "=r"(r[3]) : "r"(a));
}
__device__ __forceinline__ uint2 h4(float4 v) {
    __half2 a = __floats2half2_rn(v.x, v.y);
    __half2 b = __floats2half2_rn(v.z, v.w);
    return make_uint2(*(uint32_t*)&a, *(uint32_t*)&b);
}

// ==================== weight repacks ====================
__global__ void repack_k(const float* __restrict__ w2, const float* __restrict__ b2,
                         const float* __restrict__ gm, const float* __restrict__ bt,
                         const float* __restrict__ mu, const float* __restrict__ vr,
                         const float* __restrict__ w1, const float* __restrict__ b1,
                         const float* __restrict__ gm1, const float* __restrict__ bt1,
                         const float* __restrict__ mu1, const float* __restrict__ vr1) {
    int i = blockIdx.x * blockDim.x + threadIdx.x;
    if (i < 64 * 32 * 9) {
        int oc = i / 288;
        int r  = i % 288;
        int ic = r / 9, k = r % 9;
        float sc = gm[oc] / sqrtf(vr[oc] + 1e-5f);
        g_w2f[(k * 64 + oc) * 32 + ic] = __float2half(w2[i] * sc);
    }
    if (i < 64) {
        float sc = gm[i] / sqrtf(vr[i] + 1e-5f);
        g_b2r[i] = b2[i] * sc + bt[i] - mu[i] * sc;
    }
    if (i < 288) {
        int c = i / 9;
        float sc = gm1[c] / sqrtf(vr1[c] + 1e-5f);
        g_w1f[i] = w1[i] * sc;
    }
    if (i < 32) {
        float sc = gm1[i] / sqrtf(vr1[i] + 1e-5f);
        g_b1f[i] = b1[i] * sc + bt1[i] - mu1[i] * sc;
    }
}

__global__ void wrepack_k(const float* __restrict__ fw) {
    int i = blockIdx.x * blockDim.x + threadIdx.x;   // 200704 = 256*3136/4
    if (i < 200704) {
        float4 v = ((const float4*)fw)[i];
        *(uint2*)(g_fwf + i * 4) = h4(v);
    }
}

// ==================== fused conv1 + conv2 (fp16 single-pass implicit GEMM) ====================
// smem: bias | si[30][32] | sw1[288] | A(290x40 fp16) | B(576x40 fp16)
#define A_STRIDE 40
#define OFF_SI   256
#define OFF_SW1  4096
#define OFF_A    5504
#define OFF_B    (OFF_A + 290 * A_STRIDE * 2)       // 28704
#define CV2_SMEM 75136                              // max(staging end 74784, D epi 5504+69632)

__global__ void __launch_bounds__(256, 2) conv2mma_k(const float* __restrict__ x) {
    extern __shared__ char smem[];
    int tid = threadIdx.x, wid = tid >> 5, lane = tid & 31;
    int b = blockIdx.x;
    float* sbias = (float*)smem;
    float (*si)[32] = (float(*)[32])(smem + OFF_SI);
    float* sw1 = (float*)(smem + OFF_SW1);
    __half* sA = (__half*)(smem + OFF_A);
    __half* sB = (__half*)(smem + OFF_B);

    if (tid < 64) sbias[tid] = g_b2r[tid];
    for (int i = tid; i < 30 * 32; i += 256) ((float*)si)[i] = 0.f;
    for (int u = tid; u < 290 * 5; u += 256)                   // zero A plane (halo stays 0)
        *(uint4*)(sA + u * 8) = make_uint4(0, 0, 0, 0);
    for (int i = tid; i < 288; i += 256) sw1[i] = g_w1f[i];
    __syncthreads();

    for (int i = tid; i < 784; i += 256) {
        int y = i / 28, xx = i % 28;
        si[y + 1][xx + 1] = x[b * 784 + i];
    }
    __syncthreads();

    // ---- conv1 + bn + relu + maxpool -> A tile (fp16) ----
    for (int idx = tid; idx < 32 * 196; idx += 256) {
        int c = idx & 31, pp = idx >> 5;
        int py = pp / 14, px = pp % 14;
        int iy = 2 * py, ix = 2 * px;
        float wk[9];
#pragma unroll
        for (int k = 0; k < 9; k++) wk[k] = sw1[c * 9 + k];
        float p[4][4];
#pragma unroll
        for (int r = 0; r < 4; r++)
#pragma unroll
            for (int cc = 0; cc < 4; cc++) p[r][cc] = si[iy + r][ix + cc];
        float v00 = 0.f, v01 = 0.f, v10 = 0.f, v11 = 0.f;
#pragma unroll
        for (int ky = 0; ky < 3; ky++)
#pragma unroll
            for (int kx = 0; kx < 3; kx++) {
                float w = wk[ky * 3 + kx];
                v00 += w * p[ky][kx];     v01 += w * p[ky][kx + 1];
                v10 += w * p[ky + 1][kx]; v11 += w * p[ky + 1][kx + 1];
            }
        float m = fmaxf(fmaxf(v00, v01), fmaxf(v10, v11)) + g_b1f[c];
        float v = fmaxf(m, 0.f);
        int row = (py + 1) * 16 + (px + 1) + 17;
        sA[row * A_STRIDE + c] = __float2half(v);
    }
    for (int u = tid; u < 576 * 4; u += 256) {
        int row = u >> 2, c8 = u & 3;
        *(uint4*)(sB + row * A_STRIDE + c8 * 8) = *(const uint4*)(g_w2f + row * 32 + c8 * 8);
    }
    __syncthreads();

    int gr = lane >> 2, ct = lane & 3;
    int r_ = lane & 7, sel = lane >> 3;
    int a_roff = ((sel & 1) << 3) + r_;
    int a_koff = (sel >> 1) << 3;
    int b_noff = ((sel >> 1) << 3) + r_;
    int b_koff = (sel & 1) << 3;

    float acc[2][8][4];
#pragma unroll
    for (int mt = 0; mt < 2; mt++)
#pragma unroll
        for (int j = 0; j < 8; j++)
#pragma unroll
            for (int q = 0; q < 4; q++) acc[mt][j][q] = 0.f;

    int r0 = wid * 32;
#pragma unroll
    for (int pos = 0; pos < 9; pos++) {
        int ky = pos / 3, kx = pos % 3;
        int arow = r0 + (ky - 1) * 16 + (kx - 1) + 17;
#pragma unroll
        for (int s = 0; s < 2; s++) {
            int kb = s * 16;
            uint32_t ah[2][4], bh[4][4];
#pragma unroll
            for (int mt = 0; mt < 2; mt++)
                ldsm4h(ah[mt], sA + (arow + mt * 16 + a_roff) * A_STRIDE + kb + a_koff);
#pragma unroll
            for (int jp = 0; jp < 4; jp++)
                ldsm4h(bh[jp], sB + (pos * 64 + jp * 16 + b_noff) * A_STRIDE + kb + b_koff);
#pragma unroll
            for (int mt = 0; mt < 2; mt++)
#pragma unroll
                for (int j = 0; j < 8; j++)
                    mma16816h(acc[mt][j], ah[mt][0], ah[mt][1], ah[mt][2], ah[mt][3],
                              bh[j >> 1][(j & 1) * 2], bh[j >> 1][(j & 1) * 2 + 1]);
        }
    }

    __syncthreads();
    float* D = (float*)(smem + OFF_A);
#pragma unroll
    for (int mt = 0; mt < 2; mt++)
#pragma unroll
        for (int j = 0; j < 8; j++) {
            int row = r0 + mt * 16 + gr;
            int col = j * 8 + ct * 2;
            *(float2*)(D + row * 68 + col)        = make_float2(acc[mt][j][0], acc[mt][j][1]);
            *(float2*)(D + (row + 8) * 68 + col)  = make_float2(acc[mt][j][2], acc[mt][j][3]);
        }
    __syncthreads();

    // epilogue: bias+relu+pool, write fp16 (fc input)
    for (int idx = tid; idx < 64 * 49; idx += 256) {
        int oc = idx / 49, t = idx - oc * 49;
        int py = t / 7, px = t - py * 7;
        int s = (2 * py + 1) * 16 + (2 * px + 1);
        float v0 = D[s * 68 + oc];
        float v1 = D[(s + 1) * 68 + oc];
        float v2 = D[(s + 16) * 68 + oc];
        float v3 = D[(s + 17) * 68 + oc];
        float v = fmaxf(fmaxf(fmaxf(v0, v1), fmaxf(v2, v3)) + sbias[oc], 0.f);
        g_p2f[b * 3136 + oc * 49 + t] = __float2half(v);
    }
}

// ==================== FC 3136 -> 256, split-K(14) fp16 single-pass HMMA ====================
#define FCS 40
__global__ void __launch_bounds__(256) fc_mma_k() {
    __shared__ __half sA[128 * FCS];
    __shared__ __half sW[64 * FCS];
    int tid = threadIdx.x, wid = tid >> 5, lane = tid & 31;
    int bm = blockIdx.x * 128, bn = blockIdx.y * 64, kz = blockIdx.z;
    int wm = wid & 3, wn = wid >> 2;
    int gr = lane >> 2, ct = lane & 3;

    float acc[2][4][4];
#pragma unroll
    for (int mt = 0; mt < 2; mt++)
#pragma unroll
        for (int n = 0; n < 4; n++)
#pragma unroll
            for (int q = 0; q < 4; q++) acc[mt][n][q] = 0.f;

    int k0 = kz * FC_KC;
    for (int kt = 0; kt < FC_KC / 32; kt++, k0 += 32) {
#pragma unroll
        for (int u = tid; u < 512; u += 256) {
            int row = u >> 2, c8 = u & 3;
            long g = (long)(bm + row) * 3136 + k0 + c8 * 8;
            *(uint4*)(sA + row * FCS + c8 * 8) = *(const uint4*)(g_p2f + g);
        }
#pragma unroll
        for (int u = tid; u < 256; u += 256) {
            int row = u >> 2, c8 = u & 3;
            long g = (long)(bn + row) * 3136 + k0 + c8 * 8;
            *(uint4*)(sW + row * FCS + c8 * 8) = *(const uint4*)(g_fwf + g);
        }
        __syncthreads();

#pragma unroll
        for (int s = 0; s < 2; s++) {
            int kb = s * 16;
            uint32_t ah[2][4], wh[4][2];
#pragma unroll
            for (int mt = 0; mt < 2; mt++) {
                const __half* p = sA + (wm * 32 + mt * 16 + gr) * FCS + kb + ct * 2;
                ah[mt][0] = *(const uint32_t*)p;
                ah[mt][1] = *(const uint32_t*)(p + 8 * FCS);
                ah[mt][2] = *(const uint32_t*)(p + 8);
                ah[mt][3] = *(const uint32_t*)(p + 8 * FCS + 8);
            }
#pragma unroll
            for (int n = 0; n < 4; n++) {
                const __half* p = sW + (wn * 32 + n * 8 + gr) * FCS + kb + ct * 2;
                wh[n][0] = *(const uint32_t*)p;
                wh[n][1] = *(const uint32_t*)(p + 8);
            }
#pragma unroll
            for (int mt = 0; mt < 2; mt++)
#pragma unroll
                for (int n = 0; n < 4; n++)
                    mma16816h(acc[mt][n], ah[mt][0], ah[mt][1], ah[mt][2], ah[mt][3], wh[n][0], wh[n][1]);
        }
        __syncthreads();
    }

    float* op = g_fpart + kz * (NB * 256);
#pragma unroll
    for (int mt = 0; mt < 2; mt++)
#pragma unroll
        for (int n = 0; n < 4; n++) {
            int row = bm + wm * 32 + mt * 16 + gr;
            int col = bn + wn * 32 + n * 8 + ct * 2;
            *(float2*)(op + row * 256 + col)       = make_float2(acc[mt][n][0], acc[mt][n][1]);
            *(float2*)(op + (row + 8) * 256 + col) = make_float2(acc[mt][n][2], acc[mt][n][3]);
        }
}

// ==================== quantum net + fused MLP head ====================
__global__ void quantum_k(const float* __restrict__ qp, const float* __restrict__ fb,
                          const float* __restrict__ p1w, const float* __restrict__ p1b,
                          const float* __restrict__ p2w, const float* __restrict__ p2b,
                          const float* __restrict__ p3w, const float* __restrict__ p3b,
                          float* __restrict__ out) {
    __shared__ float sc_[80], ss_[80];
    __shared__ float z1s[8][128];
    __shared__ float z2s[8][64];
    int tid = threadIdx.x;
    if (tid < 80) {
        float t = qp[tid] * 0.5f;
        ss_[tid] = sinf(t);
        sc_[tid] = cosf(t);
    }
    __syncthreads();
    int warp = tid >> 5, lane = tid & 31;
    int b = blockIdx.x * 8 + warp;

    float re[8], im[8];
    {
        float4 s0 = make_float4(0.f, 0.f, 0.f, 0.f), s1 = s0;
#pragma unroll
        for (int kz = 0; kz < FC_KSPLIT; kz++) {
            const float4* pp = (const float4*)(g_fpart + kz * (NB * 256) + b * 256 + lane * 8);
            float4 a = pp[0], c = pp[1];
            s0.x += a.x; s0.y += a.y; s0.z += a.z; s0.w += a.w;
            s1.x += c.x; s1.y += c.y; s1.z += c.z; s1.w += c.w;
        }
        const float4* bp = (const float4*)(fb + lane * 8);
        float4 b0 = bp[0], b1 = bp[1];
        re[0] = tanhf(s0.x + b0.x); re[1] = tanhf(s0.y + b0.y);
        re[2] = tanhf(s0.z + b0.z); re[3] = tanhf(s0.w + b0.w);
        re[4] = tanhf(s1.x + b1.x); re[5] = tanhf(s1.y + b1.y);
        re[6] = tanhf(s1.z + b1.z); re[7] = tanhf(s1.w + b1.w);
#pragma unroll
        for (int j = 0; j < 8; j++) im[j] = 0.f;
    }

    float s2 = 0.f;
#pragma unroll
    for (int j = 0; j < 8; j++) s2 += re[j] * re[j];
#pragma unroll
    for (int o = 16; o; o >>= 1) s2 += __shfl_xor_sync(0xffffffffu, s2, o);
    float inv = rsqrtf(s2);
#pragma unroll
    for (int j = 0; j < 8; j++) re[j] *= inv;

    const float R2 = 0.7071067811865476f;
#pragma unroll
    for (int w = 0; w < 5; w++) {
        int m = 16 >> w;
        float sgn = (lane & m) ? -1.f : 1.f;
#pragma unroll
        for (int j = 0; j < 8; j++) {
            float o_ = __shfl_xor_sync(0xffffffffu, re[j], m);
            re[j] = (sgn * re[j] + o_) * R2;
        }
    }
#pragma unroll
    for (int w = 5; w < 8; w++) {
        int mm = 1 << (7 - w);
#pragma unroll
        for (int j = 0; j < 8; j++) {
            if ((j & mm) == 0) {
                int j2 = j | mm;
                float a = re[j], bb = re[j2];
                re[j] = (a + bb) * R2;
                re[j2] = (a - bb) * R2;
            }
        }
    }

    float dre[8], dim_[8];
#pragma unroll
    for (int j = 0; j < 8; j++) {
        int a = lane * 8 + j;
        int k = (2 * __popc(a & 0xAA) + __popc(a & 0x55)) & 7;
        int par = __popc(a & (a >> 1) & 0x7F) & 1;
        float sn, cs;
        sincosf(0.78539816339744831f * (float)k, &sn, &cs);
        float sg = par ? -1.f : 1.f;
        dre[j] = sg * cs;
        dim_[j] = sg * sn;
    }

    for (int layer = 0; layer < 10; layer++) {
#pragma unroll
        for (int w = 0; w < 5; w++) {
            float c = sc_[layer * 8 + w], s = ss_[layer * 8 + w];
            int m = 16 >> w;
#pragma unroll
            for (int j = 0; j < 8; j++) {
                float pre = __shfl_xor_sync(0xffffffffu, re[j], m);
                float pim = __shfl_xor_sync(0xffffffffu, im[j], m);
                float nr = c * re[j] + s * pim;
                float ni = c * im[j] - s * pre;
                re[j] = nr;
                im[j] = ni;
            }
        }
#pragma unroll
        for (int w = 5; w < 8; w++) {
            float c = sc_[layer * 8 + w], s = ss_[layer * 8 + w];
            int mm = 1 << (7 - w);
#pragma unroll
            for (int j = 0; j < 8; j++) {
                if ((j & mm) == 0) {
                    int j2 = j | mm;
                    float r0 = re[j], i0 = im[j], r1 = re[j2], i1 = im[j2];
                    re[j]  = c * r0 + s * i1;  im[j]  = c * i0 - s * r1;
                    re[j2] = c * r1 + s * i0;  im[j2] = c * i1 - s * r0;
                }
            }
        }
#pragma unroll
        for (int j = 0; j < 8; j++) {
            float r = re[j], ii = im[j];
            re[j] = r * dre[j] - ii * dim_[j];
            im[j] = r * dim_[j] + ii * dre[j];
        }
    }

    float p[8], qv[8];
#pragma unroll
    for (int j = 0; j < 8; j++) p[j] = re[j] * re[j] + im[j] * im[j];
#pragma unroll
    for (int q = 0; q < 8; q++) {
        int bp = 7 - q;
        float s_ = 0.f;
#pragma unroll
        for (int j = 0; j < 8; j++) {
            int a = lane * 8 + j;
            s_ += ((a >> bp) & 1) ? -p[j] : p[j];
        }
#pragma unroll
        for (int o = 16; o; o >>= 1) s_ += __shfl_xor_sync(0xffffffffu, s_, o);
        qv[q] = s_;
    }

    // ---- fused MLP head, in-warp ----
#pragma unroll
    for (int r = 0; r < 4; r++) {
        int o = r * 32 + lane;
        float a = p1b[o];
#pragma unroll
        for (int k = 0; k < 8; k++) a += qv[k] * p1w[o * 8 + k];
        z1s[warp][o] = fmaxf(a, 0.f);
    }
    __syncwarp();
#pragma unroll
    for (int r = 0; r < 2; r++) {
        int o = r * 32 + lane;
        float a = p2b[o];
        const float* wrow = p2w + o * 128;
        const float* z = z1s[warp];
#pragma unroll 16
        for (int k = 0; k < 128; k++) a += z[k] * wrow[k];
        z2s[warp][o] = fmaxf(a, 0.f);
    }
    __syncwarp();
    if (lane < 10) {
        float a = p3b[lane];
        const float* wrow = p3w + lane * 64;
        const float* z = z2s[warp];
#pragma unroll
        for (int k = 0; k < 64; k++) a += z[k] * wrow[k];
        out[b * 10 + lane] = a;
    }
}

// ==================== launch ====================
extern "C" void kernel_launch(void* const* d_in, const int* in_sizes, int n_in,
                              void* d_out, int out_size) {
    (void)in_sizes; (void)n_in; (void)out_size;
    const float* x   = (const float*)d_in[0];
    const float* c1w = (const float*)d_in[1];
    const float* c1b = (const float*)d_in[2];
    const float* g1  = (const float*)d_in[3];
    const float* be1 = (const float*)d_in[4];
    const float* m1  = (const float*)d_in[5];
    const float* v1  = (const float*)d_in[6];
    const float* c2w = (const float*)d_in[7];
    const float* c2b = (const float*)d_in[8];
    const float* g2  = (const float*)d_in[9];
    const float* be2 = (const float*)d_in[10];
    const float* m2  = (const float*)d_in[11];
    const float* v2  = (const float*)d_in[12];
    const float* fw  = (const float*)d_in[13];
    const float* fb  = (const float*)d_in[14];
    const float* qp  = (const float*)d_in[15];
    const float* p1w = (const float*)d_in[16];
    const float* p1b = (const float*)d_in[17];
    const float* p2w = (const float*)d_in[18];
    const float* p2b = (const float*)d_in[19];
    const float* p3w = (const float*)d_in[20];
    const float* p3b = (const float*)d_in[21];
    float* out = (float*)d_out;

    cudaFuncSetAttribute(conv2mma_k, cudaFuncAttributeMaxDynamicSharedMemorySize, CV2_SMEM);

    repack_k<<<72, 256>>>(c2w, c2b, g2, be2, m2, v2, c1w, c1b, g1, be1, m1, v1);
    wrepack_k<<<784, 256>>>(fw);
    conv2mma_k<<<NB, 256, CV2_SMEM>>>(x);
    dim3 fg(8, 4, FC_KSPLIT);
    fc_mma_k<<<fg, 256>>>();
    quantum_k<<<NB / 8, 256>>>(qp, fb, p1w, p1b, p2w, p2b, p3w, p3b, out);
}